// round 11
// baseline (speedup 1.0000x reference)
#include <cuda_runtime.h>
#include <cuda_fp16.h>
#include <cstdint>

#define L 512
#define NR (L * L)           // 262144
#define C 128
typedef __half f16;

// ---------------- scratch ----------------------------------------------------
__device__ f16   g_zn[(size_t)NR * C];    // z_norm fp16 [r][c]
__device__ f16   g_at[(size_t)NR * C];    // a transposed fp16 [c][i*512+k]
__device__ f16   g_bt[(size_t)NR * C];    // b transposed fp16 [c][j*512+k]
__device__ f16   g_gate[(size_t)NR * C];  // sigmoid gate fp16 [r][c]
__device__ float g_xt[(size_t)NR * C];    // contraction out fp32 [c][i*512+j]
__device__ f16   g_xn[(size_t)NR * C];    // LN-out normalized fp16 [r][c]
__device__ float g_rsq[NR];               // 1/sqrt(max(valid_k,1))
__device__ f16   g_wb[6 * C * C];         // fp16 weights: Wap,Wbp,Wag,Wbg,Wg,Wo

__device__ __forceinline__ float sigm(float x) { return 1.f / (1.f + __expf(-x)); }

// ---------------- PTX helpers (plain sm_80+ PTX only) ------------------------
__device__ __forceinline__ uint32_t smem_u32(const void* p) {
    uint32_t a;
    asm("{ .reg .u64 t; cvta.to.shared.u64 t, %1; cvt.u32.u64 %0, t; }" : "=r"(a) : "l"(p));
    return a;
}
__device__ __forceinline__ void cpa16(uint32_t dst, const void* src) {
    asm volatile("cp.async.cg.shared.global [%0], [%1], 16;" :: "r"(dst), "l"(src));
}
__device__ __forceinline__ void cpa_commit() { asm volatile("cp.async.commit_group;" ::: "memory"); }
template <int N> __device__ __forceinline__ void cpa_wait() {
    asm volatile("cp.async.wait_group %0;" :: "n"(N) : "memory");
}
__device__ __forceinline__ void ldsm4(uint32_t (&r)[4], uint32_t addr) {
    asm volatile("ldmatrix.sync.aligned.m8n8.x4.shared.b16 {%0,%1,%2,%3}, [%4];"
                 : "=r"(r[0]), "=r"(r[1]), "=r"(r[2]), "=r"(r[3]) : "r"(addr));
}
__device__ __forceinline__ void mma16816(float (&d)[4], const uint32_t (&a)[4],
                                         uint32_t b0, uint32_t b1) {
    asm volatile("mma.sync.aligned.m16n8k16.row.col.f32.f16.f16.f32 "
                 "{%0,%1,%2,%3}, {%4,%5,%6,%7}, {%8,%9}, {%0,%1,%2,%3};"
                 : "+f"(d[0]), "+f"(d[1]), "+f"(d[2]), "+f"(d[3])
                 : "r"(a[0]), "r"(a[1]), "r"(a[2]), "r"(a[3]), "r"(b0), "r"(b1));
}
// A fragment (m16k16, row-major src): rows mrow.., cols kc..
__device__ __forceinline__ uint32_t a_addr(uint32_t base, int mrow, int kc, int P, int lane) {
    return base + (uint32_t)((mrow + (lane & 15)) * P + kc + ((lane >> 4) << 3)) * 2;
}
// B fragment pair (two n8 tiles, k16), src rows = n (k-contiguous)
__device__ __forceinline__ uint32_t b_addr(uint32_t base, int nrow, int kc, int P, int lane) {
    return base + (uint32_t)((nrow + (lane & 7) + ((lane >> 4) << 3)) * P + kc +
                             (((lane >> 3) & 1) << 3)) * 2;
}

// stage a fp16 row-major [128r][128c] tile into pitched smem (pitch 136 hw)
#define PP 136
__device__ __forceinline__ void stage128(uint32_t dst, const f16* __restrict__ src, int t) {
    #pragma unroll
    for (int i = 0; i < 8; i++) {
        int idx = t + i * 256;
        int r = idx >> 4, s8 = (idx & 15) << 3;
        cpa16(dst + (uint32_t)(r * PP + s8) * 2, src + (size_t)r * C + s8);
    }
}

// warp GEMM: acc[16][4] += A(16x128, cached frags) * W^T(128x128 from smem)
__device__ __forceinline__ void gemm_w(float (*acc)[4], const uint32_t a_all[8][4],
                                       uint32_t wbase, int lane) {
    #pragma unroll
    for (int nt2 = 0; nt2 < 8; nt2++) {
        #pragma unroll
        for (int kk = 0; kk < 8; kk++) {
            uint32_t b[4];
            ldsm4(b, b_addr(wbase, nt2 * 16, kk * 16, PP, lane));
            mma16816(acc[nt2 * 2],     a_all[kk], b[0], b[1]);
            mma16816(acc[nt2 * 2 + 1], a_all[kk], b[2], b[3]);
        }
    }
}

// ---------------- K1: input LayerNorm -> fp16 -------------------------------
__global__ __launch_bounds__(256) void k_ln_in(const float* __restrict__ z,
                                               const float* __restrict__ g,
                                               const float* __restrict__ b) {
    int w = threadIdx.x >> 5, l = threadIdx.x & 31;
    size_t row = (size_t)blockIdx.x * 8 + w;
    float4 v = *(const float4*)&z[row * C + l * 4];
    float s = v.x + v.y + v.z + v.w;
    float s2 = v.x * v.x + v.y * v.y + v.z * v.z + v.w * v.w;
    #pragma unroll
    for (int o = 16; o > 0; o >>= 1) {
        s += __shfl_xor_sync(0xFFFFFFFFu, s, o);
        s2 += __shfl_xor_sync(0xFFFFFFFFu, s2, o);
    }
    float mu = s * (1.f / 128.f);
    float var = s2 * (1.f / 128.f) - mu * mu;
    float rs = rsqrtf(var + 1e-5f);
    float4 gg = *(const float4*)&g[l * 4];
    float4 bb = *(const float4*)&b[l * 4];
    __half2 p0 = __floats2half2_rn((v.x - mu) * rs * gg.x + bb.x,
                                   (v.y - mu) * rs * gg.y + bb.y);
    __half2 p1 = __floats2half2_rn((v.z - mu) * rs * gg.z + bb.z,
                                   (v.w - mu) * rs * gg.w + bb.w);
    uint2 pk = make_uint2(*reinterpret_cast<uint32_t*>(&p0), *reinterpret_cast<uint32_t*>(&p1));
    *reinterpret_cast<uint2*>(&g_zn[row * C + l * 4]) = pk;
}

// ---------------- K2: rsq ----------------------------------------------------
__global__ void k_rsq(const float* __restrict__ mask) {
    __shared__ float mi[8][512];
    int i0 = blockIdx.x * 8;
    int tid = threadIdx.x;
    for (int idx = tid; idx < 8 * 512; idx += 256)
        mi[idx >> 9][idx & 511] = mask[(size_t)(i0 + (idx >> 9)) * L + (idx & 511)];
    __syncthreads();
    for (int j = tid; j < L; j += 256) {
        float s[8];
        #pragma unroll
        for (int ii = 0; ii < 8; ii++) s[ii] = 0.f;
        for (int k = 0; k < L; k += 4) {
            float4 m4 = *(const float4*)&mask[(size_t)j * L + k];
            float mv[4] = {m4.x, m4.y, m4.z, m4.w};
            #pragma unroll
            for (int q = 0; q < 4; q++)
                #pragma unroll
                for (int ii = 0; ii < 8; ii++) s[ii] = fmaf(mi[ii][k + q], mv[q], s[ii]);
        }
        #pragma unroll
        for (int ii = 0; ii < 8; ii++)
            g_rsq[(size_t)(i0 + ii) * L + j] = rsqrtf(fmaxf(s[ii], 1.f));
    }
}

// ---------------- K0: weights fp32 -> fp16 -----------------------------------
__global__ void k_wconv(const float* __restrict__ Wap, const float* __restrict__ Wbp,
                        const float* __restrict__ Wag, const float* __restrict__ Wbg,
                        const float* __restrict__ Wg,  const float* __restrict__ Wo) {
    const float* src[6] = {Wap, Wbp, Wag, Wbg, Wg, Wo};
    int m = blockIdx.y;
    const float* W = src[m];
    int idx = (blockIdx.x * 256 + threadIdx.x) * 4;
    float4 v = *(const float4*)&W[idx];
    __half2 p0 = __floats2half2_rn(v.x, v.y);
    __half2 p1 = __floats2half2_rn(v.z, v.w);
    *(uint2*)&g_wb[m * 16384 + idx] =
        make_uint2(*reinterpret_cast<uint32_t*>(&p0), *reinterpret_cast<uint32_t*>(&p1));
}

// ---------------- K3: fused projections (HMMA) -------------------------------
#define PROJ_SMEM (34816 * 2 + 5 * 128 * 4)

__global__ __launch_bounds__(256) void k_proj(
    const float* __restrict__ bap, const float* __restrict__ bag,
    const float* __restrict__ bbp, const float* __restrict__ bbg,
    const float* __restrict__ bgp, const float* __restrict__ mask) {
    extern __shared__ char sm[];
    const uint32_t sb = smem_u32(sm);
    const uint32_t Xs = sb, Ws = sb + 34816;
    f16* stage = (f16*)(sm + 34816);    // aliases Ws (used after GEMMs)
    float* sbias = (float*)(sm + 69632);
    const int t = threadIdx.x, lane = t & 31, w = t >> 5;
    const size_t r0 = (size_t)blockIdx.x * 128;

    stage128(Xs, g_zn + r0 * C, t);
    cpa_commit();
    if (t < 128) {
        sbias[t] = bap[t]; sbias[128 + t] = bag[t]; sbias[256 + t] = bbp[t];
        sbias[384 + t] = bbg[t]; sbias[512 + t] = bgp[t];
    }
    cpa_wait<0>();
    __syncthreads();

    uint32_t a_all[8][4];
    #pragma unroll
    for (int kk = 0; kk < 8; kk++)
        ldsm4(a_all[kk], a_addr(Xs, w * 16, kk * 16, PP, lane));

    const float m0 = mask[r0 + w * 16 + (lane >> 2)];
    const float m1 = mask[r0 + w * 16 + 8 + (lane >> 2)];

    #pragma unroll 1
    for (int pass = 0; pass < 2; pass++) {
        stage128(Ws, g_wb + (size_t)pass * 16384, t);       // Wap / Wbp
        cpa_commit(); cpa_wait<0>(); __syncthreads();
        float accP[16][4];
        #pragma unroll
        for (int i = 0; i < 16; i++)
            #pragma unroll
            for (int q = 0; q < 4; q++) accP[i][q] = 0.f;
        gemm_w(accP, a_all, Ws, lane);
        __syncthreads();

        stage128(Ws, g_wb + (size_t)(2 + pass) * 16384, t); // Wag / Wbg
        cpa_commit(); cpa_wait<0>(); __syncthreads();
        float accG[16][4];
        #pragma unroll
        for (int i = 0; i < 16; i++)
            #pragma unroll
            for (int q = 0; q < 4; q++) accG[i][q] = 0.f;
        gemm_w(accG, a_all, Ws, lane);
        __syncthreads();

        const float* bP = sbias + pass * 256;
        const float* bG = bP + 128;
        f16* outg = pass ? g_bt : g_at;

        #pragma unroll
        for (int nt = 0; nt < 16; nt++) {
            int col = nt * 8 + (lane & 3) * 2;
            int row0 = w * 16 + (lane >> 2), row1 = row0 + 8;
            float bp0 = bP[col], bp1 = bP[col + 1];
            float bg0 = bG[col], bg1 = bG[col + 1];
            stage[col * 128 + row0]       = __float2half((accP[nt][0] + bp0) * sigm(accG[nt][0] + bg0) * m0);
            stage[(col + 1) * 128 + row0] = __float2half((accP[nt][1] + bp1) * sigm(accG[nt][1] + bg1) * m0);
            stage[col * 128 + row1]       = __float2half((accP[nt][2] + bp0) * sigm(accG[nt][2] + bg0) * m1);
            stage[(col + 1) * 128 + row1] = __float2half((accP[nt][3] + bp1) * sigm(accG[nt][3] + bg1) * m1);
        }
        __syncthreads();
        #pragma unroll
        for (int i = 0; i < 8; i++) {
            int idx = t + i * 256, cc = idx >> 4, seg = (idx & 15) << 3;
            *(uint4*)&outg[(size_t)cc * NR + r0 + seg] = *(const uint4*)&stage[cc * 128 + seg];
        }
        __syncthreads();
    }

    // gate pass: sigm(zn Wg + bg), row-major
    stage128(Ws, g_wb + 4 * 16384, t);
    cpa_commit(); cpa_wait<0>(); __syncthreads();
    float accP[16][4];
    #pragma unroll
    for (int i = 0; i < 16; i++)
        #pragma unroll
        for (int q = 0; q < 4; q++) accP[i][q] = 0.f;
    gemm_w(accP, a_all, Ws, lane);

    #pragma unroll
    for (int nt = 0; nt < 16; nt++) {
        int col = nt * 8 + (lane & 3) * 2;
        int row0 = w * 16 + (lane >> 2), row1 = row0 + 8;
        float b0 = sbias[512 + col], b1 = sbias[512 + col + 1];
        __half2 h0 = __floats2half2_rn(sigm(accP[nt][0] + b0), sigm(accP[nt][1] + b1));
        __half2 h1 = __floats2half2_rn(sigm(accP[nt][2] + b0), sigm(accP[nt][3] + b1));
        *(uint32_t*)&g_gate[(r0 + row0) * C + col] = *reinterpret_cast<uint32_t*>(&h0);
        *(uint32_t*)&g_gate[(r0 + row1) * C + col] = *reinterpret_cast<uint32_t*>(&h1);
    }
}

// ---------------- K4: triangle contraction (HMMA, per channel) ---------------
#define PT 72
#define TRI_SMEM (4 * 128 * PT * 2)   // 73728

__global__ __launch_bounds__(256) void k_tri() {
    extern __shared__ char sm[];
    const uint32_t sb = smem_u32(sm);
    const int t = threadIdx.x, lane = t & 31, w = t >> 5;
    const int c = blockIdx.z, i0 = blockIdx.y * 128, j0 = blockIdx.x * 128;
    const f16* A = g_at + (size_t)c * NR + (size_t)i0 * L;
    const f16* Bg = g_bt + (size_t)c * NR + (size_t)j0 * L;
    const uint32_t Ab[2] = {sb, sb + 18432};
    const uint32_t Bb[2] = {sb + 36864, sb + 55296};

    // preload chunk 0
    {
        #pragma unroll
        for (int i = 0; i < 4; i++) {
            int idx = t + i * 256, r = idx >> 3, s = (idx & 7) << 3;
            cpa16(Ab[0] + (uint32_t)(r * PT + s) * 2, A + (size_t)r * L + s);
        }
        #pragma unroll
        for (int i = 0; i < 4; i++) {
            int idx = t + i * 256, r = idx >> 3, s = (idx & 7) << 3;
            cpa16(Bb[0] + (uint32_t)(r * PT + s) * 2, Bg + (size_t)r * L + s);
        }
        cpa_commit();
    }

    float acc[16][4];
    #pragma unroll
    for (int i = 0; i < 16; i++)
        #pragma unroll
        for (int q = 0; q < 4; q++) acc[i][q] = 0.f;
    const int wi = (w & 3) * 32, wj = (w >> 2) * 64;

    for (int kb = 0; kb < 8; kb++) {
        int b = kb & 1;
        if (kb < 7) {
            int nb = b ^ 1;
            #pragma unroll
            for (int i = 0; i < 4; i++) {
                int idx = t + i * 256, r = idx >> 3, s = (idx & 7) << 3;
                cpa16(Ab[nb] + (uint32_t)(r * PT + s) * 2, A + (size_t)r * L + (kb + 1) * 64 + s);
            }
            #pragma unroll
            for (int i = 0; i < 4; i++) {
                int idx = t + i * 256, r = idx >> 3, s = (idx & 7) << 3;
                cpa16(Bb[nb] + (uint32_t)(r * PT + s) * 2, Bg + (size_t)r * L + (kb + 1) * 64 + s);
            }
            cpa_commit();
            cpa_wait<1>();
        } else {
            cpa_wait<0>();
        }
        __syncthreads();
        #pragma unroll
        for (int kk = 0; kk < 4; kk++) {
            uint32_t a0[4], a1[4];
            ldsm4(a0, a_addr(Ab[b], wi, kk * 16, PT, lane));
            ldsm4(a1, a_addr(Ab[b], wi + 16, kk * 16, PT, lane));
            #pragma unroll
            for (int nt2 = 0; nt2 < 4; nt2++) {
                uint32_t bb[4];
                ldsm4(bb, b_addr(Bb[b], wj + nt2 * 16, kk * 16, PT, lane));
                mma16816(acc[nt2 * 2],         a0, bb[0], bb[1]);
                mma16816(acc[nt2 * 2 + 1],     a0, bb[2], bb[3]);
                mma16816(acc[8 + nt2 * 2],     a1, bb[0], bb[1]);
                mma16816(acc[8 + nt2 * 2 + 1], a1, bb[2], bb[3]);
            }
        }
        __syncthreads();
    }

    float* xp = g_xt + (size_t)c * NR;
    #pragma unroll
    for (int mt = 0; mt < 2; mt++) {
        int row0 = i0 + wi + mt * 16 + (lane >> 2);
        #pragma unroll
        for (int nt = 0; nt < 8; nt++) {
            int col = j0 + wj + nt * 8 + (lane & 3) * 2;
            float* d = acc[mt * 8 + nt];
            size_t o0 = (size_t)row0 * L + col;
            size_t o1 = (size_t)(row0 + 8) * L + col;
            float2 rv0 = *(const float2*)&g_rsq[o0];
            float2 rv1 = *(const float2*)&g_rsq[o1];
            *(float2*)&xp[o0] = make_float2(d[0] * rv0.x, d[1] * rv0.y);
            *(float2*)&xp[o1] = make_float2(d[2] * rv1.x, d[3] * rv1.y);
        }
    }
}

// ---------------- K5: LN-out stats + normalize + transpose -> fp16 [r][c] ----
__global__ __launch_bounds__(128) void k_lnT(const float* __restrict__ lng,
                                             const float* __restrict__ lnb) {
    extern __shared__ float raw[];  // [128][132]
    const int t = threadIdx.x, w = t >> 5, l = t & 31;
    const size_t r0 = (size_t)blockIdx.x * 128;
    #pragma unroll 4
    for (int cc = 0; cc < 32; cc++) {
        int c = w * 32 + cc;
        float4 v = *(const float4*)&g_xt[(size_t)c * NR + r0 + l * 4];
        *(float4*)&raw[c * 132 + l * 4] = v;
    }
    __syncthreads();
    float s = 0.f, s2 = 0.f;
    #pragma unroll 8
    for (int c = 0; c < C; c++) {
        float v = raw[c * 132 + t];
        s += v; s2 += v * v;
    }
    float mu = s * (1.f / 128.f);
    float var = s2 * (1.f / 128.f) - mu * mu;
    float rs = rsqrtf(var + 1e-5f);
    f16* xr = g_xn + (r0 + t) * C;
    #pragma unroll
    for (int seg = 0; seg < 16; seg++) {
        uint32_t u[4];
        #pragma unroll
        for (int q = 0; q < 4; q++) {
            int c = seg * 8 + q * 2;
            float v0 = (raw[c * 132 + t] - mu) * rs * lng[c] + lnb[c];
            float v1 = (raw[(c + 1) * 132 + t] - mu) * rs * lng[c + 1] + lnb[c + 1];
            __half2 p = __floats2half2_rn(v0, v1);
            u[q] = *reinterpret_cast<uint32_t*>(&p);
        }
        *reinterpret_cast<uint4*>(xr + seg * 8) = make_uint4(u[0], u[1], u[2], u[3]);
    }
}

// ---------------- K6: output GEMM + gate epilogue (HMMA) ---------------------
#define OUT_SMEM (34816 * 2 + 512)

__global__ __launch_bounds__(256) void k_out(const float* __restrict__ bo,
                                             const float* __restrict__ mask,
                                             float* __restrict__ OUT) {
    extern __shared__ char sm[];
    const uint32_t sb = smem_u32(sm);
    const uint32_t Xs = sb, Ws = sb + 34816;
    float* sbo = (float*)(sm + 69632);
    const int t = threadIdx.x, lane = t & 31, w = t >> 5;
    const size_t r0 = (size_t)blockIdx.x * 128;

    stage128(Xs, g_xn + r0 * C, t);
    stage128(Ws, g_wb + 5 * 16384, t);
    cpa_commit();
    if (t < 128) sbo[t] = bo[t];
    cpa_wait<0>();
    __syncthreads();

    uint32_t a_all[8][4];
    #pragma unroll
    for (int kk = 0; kk < 8; kk++)
        ldsm4(a_all[kk], a_addr(Xs, w * 16, kk * 16, PP, lane));

    float acc[16][4];
    #pragma unroll
    for (int i = 0; i < 16; i++)
        #pragma unroll
        for (int q = 0; q < 4; q++) acc[i][q] = 0.f;
    gemm_w(acc, a_all, Ws, lane);

    const float m0 = mask[r0 + w * 16 + (lane >> 2)];
    const float m1 = mask[r0 + w * 16 + 8 + (lane >> 2)];
    #pragma unroll
    for (int nt = 0; nt < 16; nt++) {
        int col = nt * 8 + (lane & 3) * 2;
        int row0 = w * 16 + (lane >> 2), row1 = row0 + 8;
        float b0 = sbo[col], b1 = sbo[col + 1];
        __half2 gg0 = *(const __half2*)&g_gate[(r0 + row0) * C + col];
        __half2 gg1 = *(const __half2*)&g_gate[(r0 + row1) * C + col];
        float2 o0 = make_float2((acc[nt][0] + b0) * __low2float(gg0) * m0,
                                (acc[nt][1] + b1) * __high2float(gg0) * m0);
        float2 o1 = make_float2((acc[nt][2] + b0) * __low2float(gg1) * m1,
                                (acc[nt][3] + b1) * __high2float(gg1) * m1);
        *(float2*)&OUT[(r0 + row0) * C + col] = o0;
        *(float2*)&OUT[(r0 + row1) * C + col] = o1;
    }
}

// ---------------- launch -----------------------------------------------------
extern "C" void kernel_launch(void* const* d_in, const int* in_sizes, int n_in,
                              void* d_out, int out_size) {
    const float* z       = (const float*)d_in[0];
    const float* mask    = (const float*)d_in[1];
    const float* ln_in_g = (const float*)d_in[2];
    const float* ln_in_b = (const float*)d_in[3];
    const float* Wap = (const float*)d_in[4],  *bap = (const float*)d_in[5];
    const float* Wbp = (const float*)d_in[6],  *bbp = (const float*)d_in[7];
    const float* Wag = (const float*)d_in[8],  *bag = (const float*)d_in[9];
    const float* Wbg = (const float*)d_in[10], *bbg = (const float*)d_in[11];
    const float* lng = (const float*)d_in[12], *lnb = (const float*)d_in[13];
    const float* Wo  = (const float*)d_in[14], *bo  = (const float*)d_in[15];
    const float* Wg  = (const float*)d_in[16], *bg  = (const float*)d_in[17];
    float* out = (float*)d_out;

    cudaFuncSetAttribute(k_proj, cudaFuncAttributeMaxDynamicSharedMemorySize, PROJ_SMEM);
    cudaFuncSetAttribute(k_tri,  cudaFuncAttributeMaxDynamicSharedMemorySize, TRI_SMEM);
    cudaFuncSetAttribute(k_lnT,  cudaFuncAttributeMaxDynamicSharedMemorySize, 128 * 132 * 4);
    cudaFuncSetAttribute(k_out,  cudaFuncAttributeMaxDynamicSharedMemorySize, OUT_SMEM);

    k_ln_in<<<NR / 8, 256>>>(z, ln_in_g, ln_in_b);
    k_rsq<<<64, 256>>>(mask);
    k_wconv<<<dim3(16, 6), 256>>>(Wap, Wbp, Wag, Wbg, Wg, Wo);
    k_proj<<<NR / 128, 256, PROJ_SMEM>>>(bap, bag, bbp, bbg, bg, mask);
    k_tri<<<dim3(4, 4, 128), 256, TRI_SMEM>>>();
    k_lnT<<<NR / 128, 128, 128 * 132 * 4>>>(lng, lnb);
    k_out<<<NR / 128, 256, OUT_SMEM>>>(bo, mask, out);
}

// round 14
// speedup vs baseline: 1.0000x; 1.0000x over previous
#include <cuda_runtime.h>
#include <cuda_fp16.h>
#include <cstdint>

#define L 512
#define NR (L * L)           // 262144
#define C 128
typedef __half f16;

// ---------------- scratch ----------------------------------------------------
__device__ f16   g_zn[(size_t)NR * C];    // z_norm fp16 [r][c]
__device__ f16   g_at[(size_t)NR * C];    // a transposed fp16 [c][i*512+k]
__device__ f16   g_bt[(size_t)NR * C];    // b transposed fp16 [c][j*512+k]
__device__ f16   g_gate[(size_t)NR * C];  // sigmoid gate fp16 [r][c]
__device__ float g_xt[(size_t)NR * C];    // contraction out fp32 [c][i*512+j]
__device__ f16   g_xn[(size_t)NR * C];    // LN-out normalized fp16 [r][c]
__device__ float g_rsq[NR];               // 1/sqrt(max(valid_k,1))
__device__ f16   g_wb[6 * C * C];         // fp16 weights: Wap,Wbp,Wag,Wbg,Wg,Wo

__device__ __forceinline__ float sigm(float x) { return 1.f / (1.f + __expf(-x)); }

// ---------------- PTX helpers (plain sm_80+ PTX only) ------------------------
__device__ __forceinline__ uint32_t smem_u32(const void* p) {
    uint32_t a;
    asm("{ .reg .u64 t; cvta.to.shared.u64 t, %1; cvt.u32.u64 %0, t; }" : "=r"(a) : "l"(p));
    return a;
}
__device__ __forceinline__ void cpa16(uint32_t dst, const void* src) {
    asm volatile("cp.async.cg.shared.global [%0], [%1], 16;" :: "r"(dst), "l"(src));
}
__device__ __forceinline__ void cpa_commit() { asm volatile("cp.async.commit_group;" ::: "memory"); }
template <int N> __device__ __forceinline__ void cpa_wait() {
    asm volatile("cp.async.wait_group %0;" :: "n"(N) : "memory");
}
__device__ __forceinline__ void ldsm4(uint32_t (&r)[4], uint32_t addr) {
    asm volatile("ldmatrix.sync.aligned.m8n8.x4.shared.b16 {%0,%1,%2,%3}, [%4];"
                 : "=r"(r[0]), "=r"(r[1]), "=r"(r[2]), "=r"(r[3]) : "r"(addr));
}
__device__ __forceinline__ void mma16816(float (&d)[4], const uint32_t (&a)[4],
                                         uint32_t b0, uint32_t b1) {
    asm volatile("mma.sync.aligned.m16n8k16.row.col.f32.f16.f16.f32 "
                 "{%0,%1,%2,%3}, {%4,%5,%6,%7}, {%8,%9}, {%0,%1,%2,%3};"
                 : "+f"(d[0]), "+f"(d[1]), "+f"(d[2]), "+f"(d[3])
                 : "r"(a[0]), "r"(a[1]), "r"(a[2]), "r"(a[3]), "r"(b0), "r"(b1));
}
// A fragment (m16k16, row-major src): rows mrow.., cols kc..
__device__ __forceinline__ uint32_t a_addr(uint32_t base, int mrow, int kc, int P, int lane) {
    return base + (uint32_t)((mrow + (lane & 15)) * P + kc + ((lane >> 4) << 3)) * 2;
}
// B fragment pair (two n8 tiles, k16), src rows = n (k-contiguous)
__device__ __forceinline__ uint32_t b_addr(uint32_t base, int nrow, int kc, int P, int lane) {
    return base + (uint32_t)((nrow + (lane & 7) + ((lane >> 4) << 3)) * P + kc +
                             (((lane >> 3) & 1) << 3)) * 2;
}

// stage a fp16 row-major [128r][128c] tile into pitched smem (pitch 136 hw)
#define PP 136
__device__ __forceinline__ void stage128(uint32_t dst, const f16* __restrict__ src, int t) {
    #pragma unroll
    for (int i = 0; i < 8; i++) {
        int idx = t + i * 256;
        int r = idx >> 4, s8 = (idx & 15) << 3;
        cpa16(dst + (uint32_t)(r * PP + s8) * 2, src + (size_t)r * C + s8);
    }
}

// warp GEMM: acc[16][4] += A(16x128, cached frags) * W^T(128x128 from smem)
__device__ __forceinline__ void gemm_w(float (*acc)[4], const uint32_t a_all[8][4],
                                       uint32_t wbase, int lane) {
    #pragma unroll
    for (int nt2 = 0; nt2 < 8; nt2++) {
        #pragma unroll
        for (int kk = 0; kk < 8; kk++) {
            uint32_t b[4];
            ldsm4(b, b_addr(wbase, nt2 * 16, kk * 16, PP, lane));
            mma16816(acc[nt2 * 2],     a_all[kk], b[0], b[1]);
            mma16816(acc[nt2 * 2 + 1], a_all[kk], b[2], b[3]);
        }
    }
}

// ---------------- K1: input LayerNorm -> fp16 -------------------------------
__global__ __launch_bounds__(256) void k_ln_in(const float* __restrict__ z,
                                               const float* __restrict__ g,
                                               const float* __restrict__ b) {
    int w = threadIdx.x >> 5, l = threadIdx.x & 31;
    size_t row = (size_t)blockIdx.x * 8 + w;
    float4 v = *(const float4*)&z[row * C + l * 4];
    float s = v.x + v.y + v.z + v.w;
    float s2 = v.x * v.x + v.y * v.y + v.z * v.z + v.w * v.w;
    #pragma unroll
    for (int o = 16; o > 0; o >>= 1) {
        s += __shfl_xor_sync(0xFFFFFFFFu, s, o);
        s2 += __shfl_xor_sync(0xFFFFFFFFu, s2, o);
    }
    float mu = s * (1.f / 128.f);
    float var = s2 * (1.f / 128.f) - mu * mu;
    float rs = rsqrtf(var + 1e-5f);
    float4 gg = *(const float4*)&g[l * 4];
    float4 bb = *(const float4*)&b[l * 4];
    __half2 p0 = __floats2half2_rn((v.x - mu) * rs * gg.x + bb.x,
                                   (v.y - mu) * rs * gg.y + bb.y);
    __half2 p1 = __floats2half2_rn((v.z - mu) * rs * gg.z + bb.z,
                                   (v.w - mu) * rs * gg.w + bb.w);
    uint2 pk = make_uint2(*reinterpret_cast<uint32_t*>(&p0), *reinterpret_cast<uint32_t*>(&p1));
    *reinterpret_cast<uint2*>(&g_zn[row * C + l * 4]) = pk;
}

// ---------------- K2: rsq ----------------------------------------------------
__global__ void k_rsq(const float* __restrict__ mask) {
    __shared__ float mi[8][512];
    int i0 = blockIdx.x * 8;
    int tid = threadIdx.x;
    for (int idx = tid; idx < 8 * 512; idx += 256)
        mi[idx >> 9][idx & 511] = mask[(size_t)(i0 + (idx >> 9)) * L + (idx & 511)];
    __syncthreads();
    for (int j = tid; j < L; j += 256) {
        float s[8];
        #pragma unroll
        for (int ii = 0; ii < 8; ii++) s[ii] = 0.f;
        for (int k = 0; k < L; k += 4) {
            float4 m4 = *(const float4*)&mask[(size_t)j * L + k];
            float mv[4] = {m4.x, m4.y, m4.z, m4.w};
            #pragma unroll
            for (int q = 0; q < 4; q++)
                #pragma unroll
                for (int ii = 0; ii < 8; ii++) s[ii] = fmaf(mi[ii][k + q], mv[q], s[ii]);
        }
        #pragma unroll
        for (int ii = 0; ii < 8; ii++)
            g_rsq[(size_t)(i0 + ii) * L + j] = rsqrtf(fmaxf(s[ii], 1.f));
    }
}

// ---------------- K0: weights fp32 -> fp16 -----------------------------------
__global__ void k_wconv(const float* __restrict__ Wap, const float* __restrict__ Wbp,
                        const float* __restrict__ Wag, const float* __restrict__ Wbg,
                        const float* __restrict__ Wg,  const float* __restrict__ Wo) {
    const float* src[6] = {Wap, Wbp, Wag, Wbg, Wg, Wo};
    int m = blockIdx.y;
    const float* W = src[m];
    int idx = (blockIdx.x * 256 + threadIdx.x) * 4;
    float4 v = *(const float4*)&W[idx];
    __half2 p0 = __floats2half2_rn(v.x, v.y);
    __half2 p1 = __floats2half2_rn(v.z, v.w);
    *(uint2*)&g_wb[m * 16384 + idx] =
        make_uint2(*reinterpret_cast<uint32_t*>(&p0), *reinterpret_cast<uint32_t*>(&p1));
}

// ---------------- K3: fused projections (HMMA) -------------------------------
#define PROJ_SMEM (34816 * 2 + 5 * 128 * 4)

__global__ __launch_bounds__(256) void k_proj(
    const float* __restrict__ bap, const float* __restrict__ bag,
    const float* __restrict__ bbp, const float* __restrict__ bbg,
    const float* __restrict__ bgp, const float* __restrict__ mask) {
    extern __shared__ char sm[];
    const uint32_t sb = smem_u32(sm);
    const uint32_t Xs = sb, Ws = sb + 34816;
    f16* stage = (f16*)(sm + 34816);    // aliases Ws (used after GEMMs)
    float* sbias = (float*)(sm + 69632);
    const int t = threadIdx.x, lane = t & 31, w = t >> 5;
    const size_t r0 = (size_t)blockIdx.x * 128;

    stage128(Xs, g_zn + r0 * C, t);
    cpa_commit();
    if (t < 128) {
        sbias[t] = bap[t]; sbias[128 + t] = bag[t]; sbias[256 + t] = bbp[t];
        sbias[384 + t] = bbg[t]; sbias[512 + t] = bgp[t];
    }
    cpa_wait<0>();
    __syncthreads();

    uint32_t a_all[8][4];
    #pragma unroll
    for (int kk = 0; kk < 8; kk++)
        ldsm4(a_all[kk], a_addr(Xs, w * 16, kk * 16, PP, lane));

    const float m0 = mask[r0 + w * 16 + (lane >> 2)];
    const float m1 = mask[r0 + w * 16 + 8 + (lane >> 2)];

    #pragma unroll 1
    for (int pass = 0; pass < 2; pass++) {
        stage128(Ws, g_wb + (size_t)pass * 16384, t);       // Wap / Wbp
        cpa_commit(); cpa_wait<0>(); __syncthreads();
        float accP[16][4];
        #pragma unroll
        for (int i = 0; i < 16; i++)
            #pragma unroll
            for (int q = 0; q < 4; q++) accP[i][q] = 0.f;
        gemm_w(accP, a_all, Ws, lane);
        __syncthreads();

        stage128(Ws, g_wb + (size_t)(2 + pass) * 16384, t); // Wag / Wbg
        cpa_commit(); cpa_wait<0>(); __syncthreads();
        float accG[16][4];
        #pragma unroll
        for (int i = 0; i < 16; i++)
            #pragma unroll
            for (int q = 0; q < 4; q++) accG[i][q] = 0.f;
        gemm_w(accG, a_all, Ws, lane);
        __syncthreads();

        const float* bP = sbias + pass * 256;
        const float* bG = bP + 128;
        f16* outg = pass ? g_bt : g_at;

        #pragma unroll
        for (int nt = 0; nt < 16; nt++) {
            int col = nt * 8 + (lane & 3) * 2;
            int row0 = w * 16 + (lane >> 2), row1 = row0 + 8;
            float bp0 = bP[col], bp1 = bP[col + 1];
            float bg0 = bG[col], bg1 = bG[col + 1];
            stage[col * 128 + row0]       = __float2half((accP[nt][0] + bp0) * sigm(accG[nt][0] + bg0) * m0);
            stage[(col + 1) * 128 + row0] = __float2half((accP[nt][1] + bp1) * sigm(accG[nt][1] + bg1) * m0);
            stage[col * 128 + row1]       = __float2half((accP[nt][2] + bp0) * sigm(accG[nt][2] + bg0) * m1);
            stage[(col + 1) * 128 + row1] = __float2half((accP[nt][3] + bp1) * sigm(accG[nt][3] + bg1) * m1);
        }
        __syncthreads();
        #pragma unroll
        for (int i = 0; i < 8; i++) {
            int idx = t + i * 256, cc = idx >> 4, seg = (idx & 15) << 3;
            *(uint4*)&outg[(size_t)cc * NR + r0 + seg] = *(const uint4*)&stage[cc * 128 + seg];
        }
        __syncthreads();
    }

    // gate pass: sigm(zn Wg + bg), row-major
    stage128(Ws, g_wb + 4 * 16384, t);
    cpa_commit(); cpa_wait<0>(); __syncthreads();
    float accP[16][4];
    #pragma unroll
    for (int i = 0; i < 16; i++)
        #pragma unroll
        for (int q = 0; q < 4; q++) accP[i][q] = 0.f;
    gemm_w(accP, a_all, Ws, lane);

    #pragma unroll
    for (int nt = 0; nt < 16; nt++) {
        int col = nt * 8 + (lane & 3) * 2;
        int row0 = w * 16 + (lane >> 2), row1 = row0 + 8;
        float b0 = sbias[512 + col], b1 = sbias[512 + col + 1];
        __half2 h0 = __floats2half2_rn(sigm(accP[nt][0] + b0), sigm(accP[nt][1] + b1));
        __half2 h1 = __floats2half2_rn(sigm(accP[nt][2] + b0), sigm(accP[nt][3] + b1));
        *(uint32_t*)&g_gate[(r0 + row0) * C + col] = *reinterpret_cast<uint32_t*>(&h0);
        *(uint32_t*)&g_gate[(r0 + row1) * C + col] = *reinterpret_cast<uint32_t*>(&h1);
    }
}

// ---------------- K4: triangle contraction (HMMA, per channel) ---------------
#define PT 72
#define TRI_SMEM (4 * 128 * PT * 2)   // 73728

__global__ __launch_bounds__(256) void k_tri() {
    extern __shared__ char sm[];
    const uint32_t sb = smem_u32(sm);
    const int t = threadIdx.x, lane = t & 31, w = t >> 5;
    const int c = blockIdx.z, i0 = blockIdx.y * 128, j0 = blockIdx.x * 128;
    const f16* A = g_at + (size_t)c * NR + (size_t)i0 * L;
    const f16* Bg = g_bt + (size_t)c * NR + (size_t)j0 * L;
    const uint32_t Ab[2] = {sb, sb + 18432};
    const uint32_t Bb[2] = {sb + 36864, sb + 55296};

    // preload chunk 0
    {
        #pragma unroll
        for (int i = 0; i < 4; i++) {
            int idx = t + i * 256, r = idx >> 3, s = (idx & 7) << 3;
            cpa16(Ab[0] + (uint32_t)(r * PT + s) * 2, A + (size_t)r * L + s);
        }
        #pragma unroll
        for (int i = 0; i < 4; i++) {
            int idx = t + i * 256, r = idx >> 3, s = (idx & 7) << 3;
            cpa16(Bb[0] + (uint32_t)(r * PT + s) * 2, Bg + (size_t)r * L + s);
        }
        cpa_commit();
    }

    float acc[16][4];
    #pragma unroll
    for (int i = 0; i < 16; i++)
        #pragma unroll
        for (int q = 0; q < 4; q++) acc[i][q] = 0.f;
    const int wi = (w & 3) * 32, wj = (w >> 2) * 64;

    for (int kb = 0; kb < 8; kb++) {
        int b = kb & 1;
        if (kb < 7) {
            int nb = b ^ 1;
            #pragma unroll
            for (int i = 0; i < 4; i++) {
                int idx = t + i * 256, r = idx >> 3, s = (idx & 7) << 3;
                cpa16(Ab[nb] + (uint32_t)(r * PT + s) * 2, A + (size_t)r * L + (kb + 1) * 64 + s);
            }
            #pragma unroll
            for (int i = 0; i < 4; i++) {
                int idx = t + i * 256, r = idx >> 3, s = (idx & 7) << 3;
                cpa16(Bb[nb] + (uint32_t)(r * PT + s) * 2, Bg + (size_t)r * L + (kb + 1) * 64 + s);
            }
            cpa_commit();
            cpa_wait<1>();
        } else {
            cpa_wait<0>();
        }
        __syncthreads();
        #pragma unroll
        for (int kk = 0; kk < 4; kk++) {
            uint32_t a0[4], a1[4];
            ldsm4(a0, a_addr(Ab[b], wi, kk * 16, PT, lane));
            ldsm4(a1, a_addr(Ab[b], wi + 16, kk * 16, PT, lane));
            #pragma unroll
            for (int nt2 = 0; nt2 < 4; nt2++) {
                uint32_t bb[4];
                ldsm4(bb, b_addr(Bb[b], wj + nt2 * 16, kk * 16, PT, lane));
                mma16816(acc[nt2 * 2],         a0, bb[0], bb[1]);
                mma16816(acc[nt2 * 2 + 1],     a0, bb[2], bb[3]);
                mma16816(acc[8 + nt2 * 2],     a1, bb[0], bb[1]);
                mma16816(acc[8 + nt2 * 2 + 1], a1, bb[2], bb[3]);
            }
        }
        __syncthreads();
    }

    float* xp = g_xt + (size_t)c * NR;
    #pragma unroll
    for (int mt = 0; mt < 2; mt++) {
        int row0 = i0 + wi + mt * 16 + (lane >> 2);
        #pragma unroll
        for (int nt = 0; nt < 8; nt++) {
            int col = j0 + wj + nt * 8 + (lane & 3) * 2;
            float* d = acc[mt * 8 + nt];
            size_t o0 = (size_t)row0 * L + col;
            size_t o1 = (size_t)(row0 + 8) * L + col;
            float2 rv0 = *(const float2*)&g_rsq[o0];
            float2 rv1 = *(const float2*)&g_rsq[o1];
            *(float2*)&xp[o0] = make_float2(d[0] * rv0.x, d[1] * rv0.y);
            *(float2*)&xp[o1] = make_float2(d[2] * rv1.x, d[3] * rv1.y);
        }
    }
}

// ---------------- K5: LN-out stats + normalize + transpose -> fp16 [r][c] ----
__global__ __launch_bounds__(128) void k_lnT(const float* __restrict__ lng,
                                             const float* __restrict__ lnb) {
    extern __shared__ float raw[];  // [128][132]
    const int t = threadIdx.x, w = t >> 5, l = t & 31;
    const size_t r0 = (size_t)blockIdx.x * 128;
    #pragma unroll 4
    for (int cc = 0; cc < 32; cc++) {
        int c = w * 32 + cc;
        float4 v = *(const float4*)&g_xt[(size_t)c * NR + r0 + l * 4];
        *(float4*)&raw[c * 132 + l * 4] = v;
    }
    __syncthreads();
    float s = 0.f, s2 = 0.f;
    #pragma unroll 8
    for (int c = 0; c < C; c++) {
        float v = raw[c * 132 + t];
        s += v; s2 += v * v;
    }
    float mu = s * (1.f / 128.f);
    float var = s2 * (1.f / 128.f) - mu * mu;
    float rs = rsqrtf(var + 1e-5f);
    f16* xr = g_xn + (r0 + t) * C;
    #pragma unroll
    for (int seg = 0; seg < 16; seg++) {
        uint32_t u[4];
        #pragma unroll
        for (int q = 0; q < 4; q++) {
            int c = seg * 8 + q * 2;
            float v0 = (raw[c * 132 + t] - mu) * rs * lng[c] + lnb[c];
            float v1 = (raw[(c + 1) * 132 + t] - mu) * rs * lng[c + 1] + lnb[c + 1];
            __half2 p = __floats2half2_rn(v0, v1);
            u[q] = *reinterpret_cast<uint32_t*>(&p);
        }
        *reinterpret_cast<uint4*>(xr + seg * 8) = make_uint4(u[0], u[1], u[2], u[3]);
    }
}

// ---------------- K6: output GEMM + gate epilogue (HMMA) ---------------------
#define OUT_SMEM (34816 * 2 + 512)

__global__ __launch_bounds__(256) void k_out(const float* __restrict__ bo,
                                             const float* __restrict__ mask,
                                             float* __restrict__ OUT) {
    extern __shared__ char sm[];
    const uint32_t sb = smem_u32(sm);
    const uint32_t Xs = sb, Ws = sb + 34816;
    float* sbo = (float*)(sm + 69632);
    const int t = threadIdx.x, lane = t & 31, w = t >> 5;
    const size_t r0 = (size_t)blockIdx.x * 128;

    stage128(Xs, g_xn + r0 * C, t);
    stage128(Ws, g_wb + 5 * 16384, t);
    cpa_commit();
    if (t < 128) sbo[t] = bo[t];
    cpa_wait<0>();
    __syncthreads();

    uint32_t a_all[8][4];
    #pragma unroll
    for (int kk = 0; kk < 8; kk++)
        ldsm4(a_all[kk], a_addr(Xs, w * 16, kk * 16, PP, lane));

    float acc[16][4];
    #pragma unroll
    for (int i = 0; i < 16; i++)
        #pragma unroll
        for (int q = 0; q < 4; q++) acc[i][q] = 0.f;
    gemm_w(acc, a_all, Ws, lane);

    const float m0 = mask[r0 + w * 16 + (lane >> 2)];
    const float m1 = mask[r0 + w * 16 + 8 + (lane >> 2)];
    #pragma unroll
    for (int nt = 0; nt < 16; nt++) {
        int col = nt * 8 + (lane & 3) * 2;
        int row0 = w * 16 + (lane >> 2), row1 = row0 + 8;
        float b0 = sbo[col], b1 = sbo[col + 1];
        __half2 gg0 = *(const __half2*)&g_gate[(r0 + row0) * C + col];
        __half2 gg1 = *(const __half2*)&g_gate[(r0 + row1) * C + col];
        float2 o0 = make_float2((acc[nt][0] + b0) * __low2float(gg0) * m0,
                                (acc[nt][1] + b1) * __high2float(gg0) * m0);
        float2 o1 = make_float2((acc[nt][2] + b0) * __low2float(gg1) * m1,
                                (acc[nt][3] + b1) * __high2float(gg1) * m1);
        *(float2*)&OUT[(r0 + row0) * C + col] = o0;
        *(float2*)&OUT[(r0 + row1) * C + col] = o1;
    }
}

// ---------------- launch -----------------------------------------------------
extern "C" void kernel_launch(void* const* d_in, const int* in_sizes, int n_in,
                              void* d_out, int out_size) {
    const float* z       = (const float*)d_in[0];
    const float* mask    = (const float*)d_in[1];
    const float* ln_in_g = (const float*)d_in[2];
    const float* ln_in_b = (const float*)d_in[3];
    const float* Wap = (const float*)d_in[4],  *bap = (const float*)d_in[5];
    const float* Wbp = (const float*)d_in[6],  *bbp = (const float*)d_in[7];
    const float* Wag = (const float*)d_in[8],  *bag = (const float*)d_in[9];
    const float* Wbg = (const float*)d_in[10], *bbg = (const float*)d_in[11];
    const float* lng = (const float*)d_in[12], *lnb = (const float*)d_in[13];
    const float* Wo  = (const float*)d_in[14], *bo  = (const float*)d_in[15];
    const float* Wg  = (const float*)d_in[16], *bg  = (const float*)d_in[17];
    float* out = (float*)d_out;

    cudaFuncSetAttribute(k_proj, cudaFuncAttributeMaxDynamicSharedMemorySize, PROJ_SMEM);
    cudaFuncSetAttribute(k_tri,  cudaFuncAttributeMaxDynamicSharedMemorySize, TRI_SMEM);
    cudaFuncSetAttribute(k_lnT,  cudaFuncAttributeMaxDynamicSharedMemorySize, 128 * 132 * 4);
    cudaFuncSetAttribute(k_out,  cudaFuncAttributeMaxDynamicSharedMemorySize, OUT_SMEM);

    k_ln_in<<<NR / 8, 256>>>(z, ln_in_g, ln_in_b);
    k_rsq<<<64, 256>>>(mask);
    k_wconv<<<dim3(16, 6), 256>>>(Wap, Wbp, Wag, Wbg, Wg, Wo);
    k_proj<<<NR / 128, 256, PROJ_SMEM>>>(bap, bag, bbp, bbg, bg, mask);
    k_tri<<<dim3(4, 4, 128), 256, TRI_SMEM>>>();
    k_lnT<<<NR / 128, 128, 128 * 132 * 4>>>(lng, lnb);
    k_out<<<NR / 128, 256, OUT_SMEM>>>(bo, mask, out);
}

// round 15
// speedup vs baseline: 1.0336x; 1.0336x over previous
#include <cuda_runtime.h>
#include <cuda_fp16.h>
#include <cstdint>

#define L 512
#define NR (L * L)           // 262144
#define C 128
typedef __half f16;

// ---------------- scratch ----------------------------------------------------
__device__ f16   g_zn[(size_t)NR * C];    // z_norm fp16 [r][c]
__device__ f16   g_at[(size_t)NR * C];    // a transposed fp16 [c][i*512+k]
__device__ f16   g_bt[(size_t)NR * C];    // b transposed fp16 [c][j*512+k]
__device__ f16   g_gate[(size_t)NR * C];  // sigmoid gate fp16 [r][c]
__device__ float g_xt[(size_t)NR * C];    // contraction out fp32 [c][i*512+j]
__device__ f16   g_xn[(size_t)NR * C];    // LN-out normalized fp16 [r][c]
__device__ float g_rsq[NR];               // 1/sqrt(max(valid_k,1))
__device__ f16   g_wb[6 * C * C];         // fp16 weights: Wap,Wbp,Wag,Wbg,Wg,Wo

__device__ __forceinline__ float sigm(float x) { return 1.f / (1.f + __expf(-x)); }

// ---------------- PTX helpers (plain sm_80+ PTX only) ------------------------
__device__ __forceinline__ uint32_t smem_u32(const void* p) {
    uint32_t a;
    asm("{ .reg .u64 t; cvta.to.shared.u64 t, %1; cvt.u32.u64 %0, t; }" : "=r"(a) : "l"(p));
    return a;
}
__device__ __forceinline__ void cpa16(uint32_t dst, const void* src) {
    asm volatile("cp.async.cg.shared.global [%0], [%1], 16;" :: "r"(dst), "l"(src));
}
__device__ __forceinline__ void cpa_commit() { asm volatile("cp.async.commit_group;" ::: "memory"); }
template <int N> __device__ __forceinline__ void cpa_wait() {
    asm volatile("cp.async.wait_group %0;" :: "n"(N) : "memory");
}
__device__ __forceinline__ void ldsm4(uint32_t (&r)[4], uint32_t addr) {
    asm volatile("ldmatrix.sync.aligned.m8n8.x4.shared.b16 {%0,%1,%2,%3}, [%4];"
                 : "=r"(r[0]), "=r"(r[1]), "=r"(r[2]), "=r"(r[3]) : "r"(addr));
}
__device__ __forceinline__ void mma16816(float (&d)[4], const uint32_t (&a)[4],
                                         uint32_t b0, uint32_t b1) {
    asm volatile("mma.sync.aligned.m16n8k16.row.col.f32.f16.f16.f32 "
                 "{%0,%1,%2,%3}, {%4,%5,%6,%7}, {%8,%9}, {%0,%1,%2,%3};"
                 : "+f"(d[0]), "+f"(d[1]), "+f"(d[2]), "+f"(d[3])
                 : "r"(a[0]), "r"(a[1]), "r"(a[2]), "r"(a[3]), "r"(b0), "r"(b1));
}
// A fragment (m16k16, row-major src): rows mrow.., cols kc..
__device__ __forceinline__ uint32_t a_addr(uint32_t base, int mrow, int kc, int P, int lane) {
    return base + (uint32_t)((mrow + (lane & 15)) * P + kc + ((lane >> 4) << 3)) * 2;
}
// B fragment pair (two n8 tiles, k16), src rows = n (k-contiguous)
__device__ __forceinline__ uint32_t b_addr(uint32_t base, int nrow, int kc, int P, int lane) {
    return base + (uint32_t)((nrow + (lane & 7) + ((lane >> 4) << 3)) * P + kc +
                             (((lane >> 3) & 1) << 3)) * 2;
}

// stage a fp16 row-major [128r][128c] tile into pitched smem (pitch 136 hw)
#define PP 136
__device__ __forceinline__ void stage128(uint32_t dst, const f16* __restrict__ src, int t) {
    #pragma unroll
    for (int i = 0; i < 8; i++) {
        int idx = t + i * 256;
        int r = idx >> 4, s8 = (idx & 15) << 3;
        cpa16(dst + (uint32_t)(r * PP + s8) * 2, src + (size_t)r * C + s8);
    }
}

// warp GEMM: acc[16][4] += A(16x128, cached frags) * W^T(128x128 from smem)
__device__ __forceinline__ void gemm_w(float (*acc)[4], const uint32_t a_all[8][4],
                                       uint32_t wbase, int lane) {
    #pragma unroll
    for (int nt2 = 0; nt2 < 8; nt2++) {
        #pragma unroll
        for (int kk = 0; kk < 8; kk++) {
            uint32_t b[4];
            ldsm4(b, b_addr(wbase, nt2 * 16, kk * 16, PP, lane));
            mma16816(acc[nt2 * 2],     a_all[kk], b[0], b[1]);
            mma16816(acc[nt2 * 2 + 1], a_all[kk], b[2], b[3]);
        }
    }
}

// ---------------- K1: input LayerNorm -> fp16 -------------------------------
__global__ __launch_bounds__(256) void k_ln_in(const float* __restrict__ z,
                                               const float* __restrict__ g,
                                               const float* __restrict__ b) {
    int w = threadIdx.x >> 5, l = threadIdx.x & 31;
    size_t row = (size_t)blockIdx.x * 8 + w;
    float4 v = *(const float4*)&z[row * C + l * 4];
    float s = v.x + v.y + v.z + v.w;
    float s2 = v.x * v.x + v.y * v.y + v.z * v.z + v.w * v.w;
    #pragma unroll
    for (int o = 16; o > 0; o >>= 1) {
        s += __shfl_xor_sync(0xFFFFFFFFu, s, o);
        s2 += __shfl_xor_sync(0xFFFFFFFFu, s2, o);
    }
    float mu = s * (1.f / 128.f);
    float var = s2 * (1.f / 128.f) - mu * mu;
    float rs = rsqrtf(var + 1e-5f);
    float4 gg = *(const float4*)&g[l * 4];
    float4 bb = *(const float4*)&b[l * 4];
    __half2 p0 = __floats2half2_rn((v.x - mu) * rs * gg.x + bb.x,
                                   (v.y - mu) * rs * gg.y + bb.y);
    __half2 p1 = __floats2half2_rn((v.z - mu) * rs * gg.z + bb.z,
                                   (v.w - mu) * rs * gg.w + bb.w);
    uint2 pk = make_uint2(*reinterpret_cast<uint32_t*>(&p0), *reinterpret_cast<uint32_t*>(&p1));
    *reinterpret_cast<uint2*>(&g_zn[row * C + l * 4]) = pk;
}

// ---------------- K2: rsq ----------------------------------------------------
__global__ void k_rsq(const float* __restrict__ mask) {
    __shared__ float mi[8][512];
    int i0 = blockIdx.x * 8;
    int tid = threadIdx.x;
    for (int idx = tid; idx < 8 * 512; idx += 256)
        mi[idx >> 9][idx & 511] = mask[(size_t)(i0 + (idx >> 9)) * L + (idx & 511)];
    __syncthreads();
    for (int j = tid; j < L; j += 256) {
        float s[8];
        #pragma unroll
        for (int ii = 0; ii < 8; ii++) s[ii] = 0.f;
        for (int k = 0; k < L; k += 4) {
            float4 m4 = *(const float4*)&mask[(size_t)j * L + k];
            float mv[4] = {m4.x, m4.y, m4.z, m4.w};
            #pragma unroll
            for (int q = 0; q < 4; q++)
                #pragma unroll
                for (int ii = 0; ii < 8; ii++) s[ii] = fmaf(mi[ii][k + q], mv[q], s[ii]);
        }
        #pragma unroll
        for (int ii = 0; ii < 8; ii++)
            g_rsq[(size_t)(i0 + ii) * L + j] = rsqrtf(fmaxf(s[ii], 1.f));
    }
}

// ---------------- K0: weights fp32 -> fp16 -----------------------------------
__global__ void k_wconv(const float* __restrict__ Wap, const float* __restrict__ Wbp,
                        const float* __restrict__ Wag, const float* __restrict__ Wbg,
                        const float* __restrict__ Wg,  const float* __restrict__ Wo) {
    const float* src[6] = {Wap, Wbp, Wag, Wbg, Wg, Wo};
    int m = blockIdx.y;
    const float* W = src[m];
    int idx = (blockIdx.x * 256 + threadIdx.x) * 4;
    float4 v = *(const float4*)&W[idx];
    __half2 p0 = __floats2half2_rn(v.x, v.y);
    __half2 p1 = __floats2half2_rn(v.z, v.w);
    *(uint2*)&g_wb[m * 16384 + idx] =
        make_uint2(*reinterpret_cast<uint32_t*>(&p0), *reinterpret_cast<uint32_t*>(&p1));
}

// ---------------- K3: fused projections (HMMA, pipelined weights) ------------
// smem: Xs @0 (34816) | W0 @34816 (34816) | W1 @69632 (34816) | bias @104448
#define PROJ_SMEM (34816 * 3 + 5 * 128 * 4)

__global__ __launch_bounds__(256) void k_proj(
    const float* __restrict__ bap, const float* __restrict__ bag,
    const float* __restrict__ bbp, const float* __restrict__ bbg,
    const float* __restrict__ bgp, const float* __restrict__ mask) {
    extern __shared__ char sm[];
    const uint32_t sb = smem_u32(sm);
    const uint32_t Xs = sb, W0 = sb + 34816, W1 = sb + 69632;
    f16* stage = (f16*)(sm + 34816);    // aliases W0 (used after its GEMM consumed)
    float* sbias = (float*)(sm + 104448);
    const int t = threadIdx.x, lane = t & 31, w = t >> 5;
    const size_t r0 = (size_t)blockIdx.x * 128;

    // initial loads: X, Wag (gate-a), Wap (proj-a)
    stage128(Xs, g_zn + r0 * C, t);
    stage128(W0, g_wb + 2 * 16384, t);   // Wag
    stage128(W1, g_wb + 0 * 16384, t);   // Wap
    cpa_commit();
    if (t < 128) {
        sbias[t] = bap[t]; sbias[128 + t] = bag[t]; sbias[256 + t] = bbp[t];
        sbias[384 + t] = bbg[t]; sbias[512 + t] = bgp[t];
    }
    cpa_wait<0>();
    __syncthreads();

    uint32_t a_all[8][4];
    #pragma unroll
    for (int kk = 0; kk < 8; kk++)
        ldsm4(a_all[kk], a_addr(Xs, w * 16, kk * 16, PP, lane));
    __syncthreads();                     // all warps done reading Xs

    // prefetch Wbg into Xs (Xs dead: A frags in regs)
    stage128(Xs, g_wb + 3 * 16384, t);
    cpa_commit();                        // pending: 1 (Wbg)

    const float m0 = mask[r0 + w * 16 + (lane >> 2)];
    const float m1 = mask[r0 + w * 16 + 8 + (lane >> 2)];

    float acc[16][4];
    uint32_t gate_pk[16][2];

    // ---- pass a ----
    // gate GEMM first (W0 = Wag), collapse to fp16 immediately
    #pragma unroll
    for (int i = 0; i < 16; i++)
        #pragma unroll
        for (int q = 0; q < 4; q++) acc[i][q] = 0.f;
    gemm_w(acc, a_all, W0, lane);
    #pragma unroll
    for (int nt = 0; nt < 16; nt++) {
        int col = nt * 8 + (lane & 3) * 2;
        float bg0 = sbias[128 + col], bg1 = sbias[128 + col + 1];
        __half2 h0 = __floats2half2_rn(sigm(acc[nt][0] + bg0), sigm(acc[nt][1] + bg1));
        __half2 h1 = __floats2half2_rn(sigm(acc[nt][2] + bg0), sigm(acc[nt][3] + bg1));
        gate_pk[nt][0] = *reinterpret_cast<uint32_t*>(&h0);
        gate_pk[nt][1] = *reinterpret_cast<uint32_t*>(&h1);
    }
    // proj GEMM (W1 = Wap)
    #pragma unroll
    for (int i = 0; i < 16; i++)
        #pragma unroll
        for (int q = 0; q < 4; q++) acc[i][q] = 0.f;
    gemm_w(acc, a_all, W1, lane);
    __syncthreads();                     // all warps done with W0/W1 reads

    // prefetch Wbp into W1
    stage128(W1, g_wb + 1 * 16384, t);
    cpa_commit();                        // pending: 2 (Wbg, Wbp)

    // epilogue a: combine -> stage (aliases W0) -> channel-major global
    #pragma unroll
    for (int nt = 0; nt < 16; nt++) {
        int col = nt * 8 + (lane & 3) * 2;
        int row0 = w * 16 + (lane >> 2), row1 = row0 + 8;
        float bp0 = sbias[col], bp1 = sbias[col + 1];
        float2 gf0 = __half22float2(*reinterpret_cast<__half2*>(&gate_pk[nt][0]));
        float2 gf1 = __half22float2(*reinterpret_cast<__half2*>(&gate_pk[nt][1]));
        stage[col * 128 + row0]       = __float2half((acc[nt][0] + bp0) * gf0.x * m0);
        stage[(col + 1) * 128 + row0] = __float2half((acc[nt][1] + bp1) * gf0.y * m0);
        stage[col * 128 + row1]       = __float2half((acc[nt][2] + bp0) * gf1.x * m1);
        stage[(col + 1) * 128 + row1] = __float2half((acc[nt][3] + bp1) * gf1.y * m1);
    }
    __syncthreads();
    #pragma unroll
    for (int i = 0; i < 8; i++) {
        int idx = t + i * 256, cc = idx >> 4, seg = (idx & 15) << 3;
        *(uint4*)&g_at[(size_t)cc * NR + r0 + seg] = *(const uint4*)&stage[cc * 128 + seg];
    }
    cpa_wait<1>();                       // Wbg (in Xs) landed
    __syncthreads();

    // ---- pass b ----
    // gate GEMM (Xs = Wbg)
    #pragma unroll
    for (int i = 0; i < 16; i++)
        #pragma unroll
        for (int q = 0; q < 4; q++) acc[i][q] = 0.f;
    gemm_w(acc, a_all, Xs, lane);
    #pragma unroll
    for (int nt = 0; nt < 16; nt++) {
        int col = nt * 8 + (lane & 3) * 2;
        float bg0 = sbias[384 + col], bg1 = sbias[384 + col + 1];
        __half2 h0 = __floats2half2_rn(sigm(acc[nt][0] + bg0), sigm(acc[nt][1] + bg1));
        __half2 h1 = __floats2half2_rn(sigm(acc[nt][2] + bg0), sigm(acc[nt][3] + bg1));
        gate_pk[nt][0] = *reinterpret_cast<uint32_t*>(&h0);
        gate_pk[nt][1] = *reinterpret_cast<uint32_t*>(&h1);
    }
    __syncthreads();                     // all warps done reading Xs (Wbg)

    // prefetch Wg into Xs
    stage128(Xs, g_wb + 4 * 16384, t);
    cpa_commit();                        // pending: <=2 (Wbp, Wg)
    cpa_wait<1>();                       // Wbp (in W1) landed
    __syncthreads();

    // proj GEMM (W1 = Wbp)
    #pragma unroll
    for (int i = 0; i < 16; i++)
        #pragma unroll
        for (int q = 0; q < 4; q++) acc[i][q] = 0.f;
    gemm_w(acc, a_all, W1, lane);
    __syncthreads();                     // all warps done with W0(stage reuse)/W1

    // epilogue b
    #pragma unroll
    for (int nt = 0; nt < 16; nt++) {
        int col = nt * 8 + (lane & 3) * 2;
        int row0 = w * 16 + (lane >> 2), row1 = row0 + 8;
        float bp0 = sbias[256 + col], bp1 = sbias[256 + col + 1];
        float2 gf0 = __half22float2(*reinterpret_cast<__half2*>(&gate_pk[nt][0]));
        float2 gf1 = __half22float2(*reinterpret_cast<__half2*>(&gate_pk[nt][1]));
        stage[col * 128 + row0]       = __float2half((acc[nt][0] + bp0) * gf0.x * m0);
        stage[(col + 1) * 128 + row0] = __float2half((acc[nt][1] + bp1) * gf0.y * m0);
        stage[col * 128 + row1]       = __float2half((acc[nt][2] + bp0) * gf1.x * m1);
        stage[(col + 1) * 128 + row1] = __float2half((acc[nt][3] + bp1) * gf1.y * m1);
    }
    __syncthreads();
    #pragma unroll
    for (int i = 0; i < 8; i++) {
        int idx = t + i * 256, cc = idx >> 4, seg = (idx & 15) << 3;
        *(uint4*)&g_bt[(size_t)cc * NR + r0 + seg] = *(const uint4*)&stage[cc * 128 + seg];
    }
    cpa_wait<0>();                       // Wg (in Xs) landed
    __syncthreads();

    // ---- gate pass: sigm(zn Wg + bg), row-major ----
    #pragma unroll
    for (int i = 0; i < 16; i++)
        #pragma unroll
        for (int q = 0; q < 4; q++) acc[i][q] = 0.f;
    gemm_w(acc, a_all, Xs, lane);
    #pragma unroll
    for (int nt = 0; nt < 16; nt++) {
        int col = nt * 8 + (lane & 3) * 2;
        int row0 = w * 16 + (lane >> 2), row1 = row0 + 8;
        float b0 = sbias[512 + col], b1 = sbias[512 + col + 1];
        __half2 h0 = __floats2half2_rn(sigm(acc[nt][0] + b0), sigm(acc[nt][1] + b1));
        __half2 h1 = __floats2half2_rn(sigm(acc[nt][2] + b0), sigm(acc[nt][3] + b1));
        *(uint32_t*)&g_gate[(r0 + row0) * C + col] = *reinterpret_cast<uint32_t*>(&h0);
        *(uint32_t*)&g_gate[(r0 + row1) * C + col] = *reinterpret_cast<uint32_t*>(&h1);
    }
}

// ---------------- K4: triangle contraction (HMMA, per channel) ---------------
#define PT 72
#define TRI_SMEM (4 * 128 * PT * 2)   // 73728

__global__ __launch_bounds__(256, 2) void k_tri() {
    extern __shared__ char sm[];
    const uint32_t sb = smem_u32(sm);
    const int t = threadIdx.x, lane = t & 31, w = t >> 5;
    const int c = blockIdx.z, i0 = blockIdx.y * 128, j0 = blockIdx.x * 128;
    const f16* A = g_at + (size_t)c * NR + (size_t)i0 * L;
    const f16* Bg = g_bt + (size_t)c * NR + (size_t)j0 * L;
    const uint32_t Ab[2] = {sb, sb + 18432};
    const uint32_t Bb[2] = {sb + 36864, sb + 55296};

    // preload chunk 0
    {
        #pragma unroll
        for (int i = 0; i < 4; i++) {
            int idx = t + i * 256, r = idx >> 3, s = (idx & 7) << 3;
            cpa16(Ab[0] + (uint32_t)(r * PT + s) * 2, A + (size_t)r * L + s);
        }
        #pragma unroll
        for (int i = 0; i < 4; i++) {
            int idx = t + i * 256, r = idx >> 3, s = (idx & 7) << 3;
            cpa16(Bb[0] + (uint32_t)(r * PT + s) * 2, Bg + (size_t)r * L + s);
        }
        cpa_commit();
    }

    float acc[16][4];
    #pragma unroll
    for (int i = 0; i < 16; i++)
        #pragma unroll
        for (int q = 0; q < 4; q++) acc[i][q] = 0.f;
    const int wi = (w & 3) * 32, wj = (w >> 2) * 64;

    for (int kb = 0; kb < 8; kb++) {
        int b = kb & 1;
        if (kb < 7) {
            int nb = b ^ 1;
            #pragma unroll
            for (int i = 0; i < 4; i++) {
                int idx = t + i * 256, r = idx >> 3, s = (idx & 7) << 3;
                cpa16(Ab[nb] + (uint32_t)(r * PT + s) * 2, A + (size_t)r * L + (kb + 1) * 64 + s);
            }
            #pragma unroll
            for (int i = 0; i < 4; i++) {
                int idx = t + i * 256, r = idx >> 3, s = (idx & 7) << 3;
                cpa16(Bb[nb] + (uint32_t)(r * PT + s) * 2, Bg + (size_t)r * L + (kb + 1) * 64 + s);
            }
            cpa_commit();
            cpa_wait<1>();
        } else {
            cpa_wait<0>();
        }
        __syncthreads();
        #pragma unroll
        for (int kk = 0; kk < 4; kk++) {
            uint32_t a0[4], a1[4];
            ldsm4(a0, a_addr(Ab[b], wi, kk * 16, PT, lane));
            ldsm4(a1, a_addr(Ab[b], wi + 16, kk * 16, PT, lane));
            #pragma unroll
            for (int nt2 = 0; nt2 < 4; nt2++) {
                uint32_t bb[4];
                ldsm4(bb, b_addr(Bb[b], wj + nt2 * 16, kk * 16, PT, lane));
                mma16816(acc[nt2 * 2],         a0, bb[0], bb[1]);
                mma16816(acc[nt2 * 2 + 1],     a0, bb[2], bb[3]);
                mma16816(acc[8 + nt2 * 2],     a1, bb[0], bb[1]);
                mma16816(acc[8 + nt2 * 2 + 1], a1, bb[2], bb[3]);
            }
        }
        __syncthreads();
    }

    float* xp = g_xt + (size_t)c * NR;
    #pragma unroll
    for (int mt = 0; mt < 2; mt++) {
        int row0 = i0 + wi + mt * 16 + (lane >> 2);
        #pragma unroll
        for (int nt = 0; nt < 8; nt++) {
            int col = j0 + wj + nt * 8 + (lane & 3) * 2;
            float* d = acc[mt * 8 + nt];
            size_t o0 = (size_t)row0 * L + col;
            size_t o1 = (size_t)(row0 + 8) * L + col;
            float2 rv0 = *(const float2*)&g_rsq[o0];
            float2 rv1 = *(const float2*)&g_rsq[o1];
            *(float2*)&xp[o0] = make_float2(d[0] * rv0.x, d[1] * rv0.y);
            *(float2*)&xp[o1] = make_float2(d[2] * rv1.x, d[3] * rv1.y);
        }
    }
}

// ---------------- K5: LN-out stats + normalize + transpose -> fp16 [r][c] ----
__global__ __launch_bounds__(128) void k_lnT(const float* __restrict__ lng,
                                             const float* __restrict__ lnb) {
    extern __shared__ float raw[];  // [128][132]
    const int t = threadIdx.x, w = t >> 5, l = t & 31;
    const size_t r0 = (size_t)blockIdx.x * 128;
    #pragma unroll 4
    for (int cc = 0; cc < 32; cc++) {
        int c = w * 32 + cc;
        float4 v = *(const float4*)&g_xt[(size_t)c * NR + r0 + l * 4];
        *(float4*)&raw[c * 132 + l * 4] = v;
    }
    __syncthreads();
    float s = 0.f, s2 = 0.f;
    #pragma unroll 8
    for (int c = 0; c < C; c++) {
        float v = raw[c * 132 + t];
        s += v; s2 += v * v;
    }
    float mu = s * (1.f / 128.f);
    float var = s2 * (1.f / 128.f) - mu * mu;
    float rs = rsqrtf(var + 1e-5f);
    f16* xr = g_xn + (r0 + t) * C;
    #pragma unroll
    for (int seg = 0; seg < 16; seg++) {
        uint32_t u[4];
        #pragma unroll
        for (int q = 0; q < 4; q++) {
            int c = seg * 8 + q * 2;
            float v0 = (raw[c * 132 + t] - mu) * rs * lng[c] + lnb[c];
            float v1 = (raw[(c + 1) * 132 + t] - mu) * rs * lng[c + 1] + lnb[c + 1];
            __half2 p = __floats2half2_rn(v0, v1);
            u[q] = *reinterpret_cast<uint32_t*>(&p);
        }
        *reinterpret_cast<uint4*>(xr + seg * 8) = make_uint4(u[0], u[1], u[2], u[3]);
    }
}

// ---------------- K6: output GEMM + gate epilogue (HMMA) ---------------------
#define OUT_SMEM (34816 * 2 + 512)

__global__ __launch_bounds__(256) void k_out(const float* __restrict__ bo,
                                             const float* __restrict__ mask,
                                             float* __restrict__ OUT) {
    extern __shared__ char sm[];
    const uint32_t sb = smem_u32(sm);
    const uint32_t Xs = sb, Ws = sb + 34816;
    float* sbo = (float*)(sm + 69632);
    const int t = threadIdx.x, lane = t & 31, w = t >> 5;
    const size_t r0 = (size_t)blockIdx.x * 128;

    stage128(Xs, g_xn + r0 * C, t);
    stage128(Ws, g_wb + 5 * 16384, t);
    cpa_commit();
    if (t < 128) sbo[t] = bo[t];
    cpa_wait<0>();
    __syncthreads();

    uint32_t a_all[8][4];
    #pragma unroll
    for (int kk = 0; kk < 8; kk++)
        ldsm4(a_all[kk], a_addr(Xs, w * 16, kk * 16, PP, lane));

    float acc[16][4];
    #pragma unroll
    for (int i = 0; i < 16; i++)
        #pragma unroll
        for (int q = 0; q < 4; q++) acc[i][q] = 0.f;
    gemm_w(acc, a_all, Ws, lane);

    const float m0 = mask[r0 + w * 16 + (lane >> 2)];
    const float m1 = mask[r0 + w * 16 + 8 + (lane >> 2)];
    #pragma unroll
    for (int nt = 0; nt < 16; nt++) {
        int col = nt * 8 + (lane & 3) * 2;
        int row0 = w * 16 + (lane >> 2), row1 = row0 + 8;
        float b0 = sbo[col], b1 = sbo[col + 1];
        __half2 gg0 = *(const __half2*)&g_gate[(r0 + row0) * C + col];
        __half2 gg1 = *(const __half2*)&g_gate[(r0 + row1) * C + col];
        float2 o0 = make_float2((acc[nt][0] + b0) * __low2float(gg0) * m0,
                                (acc[nt][1] + b1) * __high2float(gg0) * m0);
        float2 o1 = make_float2((acc[nt][2] + b0) * __low2float(gg1) * m1,
                                (acc[nt][3] + b1) * __high2float(gg1) * m1);
        *(float2*)&OUT[(r0 + row0) * C + col] = o0;
        *(float2*)&OUT[(r0 + row1) * C + col] = o1;
    }
}

// ---------------- launch -----------------------------------------------------
extern "C" void kernel_launch(void* const* d_in, const int* in_sizes, int n_in,
                              void* d_out, int out_size) {
    const float* z       = (const float*)d_in[0];
    const float* mask    = (const float*)d_in[1];
    const float* ln_in_g = (const float*)d_in[2];
    const float* ln_in_b = (const float*)d_in[3];
    const float* Wap = (const float*)d_in[4],  *bap = (const float*)d_in[5];
    const float* Wbp = (const float*)d_in[6],  *bbp = (const float*)d_in[7];
    const float* Wag = (const float*)d_in[8],  *bag = (const float*)d_in[9];
    const float* Wbg = (const float*)d_in[10], *bbg = (const float*)d_in[11];
    const float* lng = (const float*)d_in[12], *lnb = (const float*)d_in[13];
    const float* Wo  = (const float*)d_in[14], *bo  = (const float*)d_in[15];
    const float* Wg  = (const float*)d_in[16], *bg  = (const float*)d_in[17];
    float* out = (float*)d_out;

    cudaFuncSetAttribute(k_proj, cudaFuncAttributeMaxDynamicSharedMemorySize, PROJ_SMEM);
    cudaFuncSetAttribute(k_tri,  cudaFuncAttributeMaxDynamicSharedMemorySize, TRI_SMEM);
    cudaFuncSetAttribute(k_lnT,  cudaFuncAttributeMaxDynamicSharedMemorySize, 128 * 132 * 4);
    cudaFuncSetAttribute(k_out,  cudaFuncAttributeMaxDynamicSharedMemorySize, OUT_SMEM);

    k_ln_in<<<NR / 8, 256>>>(z, ln_in_g, ln_in_b);
    k_rsq<<<64, 256>>>(mask);
    k_wconv<<<dim3(16, 6), 256>>>(Wap, Wbp, Wag, Wbg, Wg, Wo);
    k_proj<<<NR / 128, 256, PROJ_SMEM>>>(bap, bag, bbp, bbg, bg, mask);
    k_tri<<<dim3(4, 4, 128), 256, TRI_SMEM>>>();
    k_lnT<<<NR / 128, 128, 128 * 132 * 4>>>(lng, lnb);
    k_out<<<NR / 128, 256, OUT_SMEM>>>(bo, mask, out);
}

// round 16
// speedup vs baseline: 1.2491x; 1.2085x over previous
#include <cuda_runtime.h>
#include <cuda_fp16.h>
#include <cstdint>

#define L 512
#define NR (L * L)           // 262144
#define C 128
typedef __half f16;

// ---------------- scratch ----------------------------------------------------
__device__ f16   g_zn[(size_t)NR * C];    // z_norm fp16 [r][c]
__device__ f16   g_at[(size_t)NR * C];    // a transposed fp16 [c][i*512+k]
__device__ f16   g_bt[(size_t)NR * C];    // b transposed fp16 [c][j*512+k]
__device__ f16   g_gate[(size_t)NR * C];  // sigmoid gate fp16 [r][c]
__device__ float g_xt[(size_t)NR * C];    // contraction out fp32 [c][i*512+j]
__device__ f16   g_xn[(size_t)NR * C];    // LN-out normalized fp16 [r][c]
__device__ float g_rsq[NR];               // 1/sqrt(max(valid_k,1))
__device__ f16   g_wb[6 * C * C];         // fp16 weights: Wap,Wbp,Wag,Wbg,Wg,Wo

__device__ __forceinline__ float sigm(float x) { return 1.f / (1.f + __expf(-x)); }

// ---------------- PTX helpers (plain sm_80+ PTX only) ------------------------
__device__ __forceinline__ uint32_t smem_u32(const void* p) {
    uint32_t a;
    asm("{ .reg .u64 t; cvta.to.shared.u64 t, %1; cvt.u32.u64 %0, t; }" : "=r"(a) : "l"(p));
    return a;
}
__device__ __forceinline__ void cpa16(uint32_t dst, const void* src) {
    asm volatile("cp.async.cg.shared.global [%0], [%1], 16;" :: "r"(dst), "l"(src));
}
__device__ __forceinline__ void cpa_commit() { asm volatile("cp.async.commit_group;" ::: "memory"); }
template <int N> __device__ __forceinline__ void cpa_wait() {
    asm volatile("cp.async.wait_group %0;" :: "n"(N) : "memory");
}
__device__ __forceinline__ void ldsm4(uint32_t (&r)[4], uint32_t addr) {
    asm volatile("ldmatrix.sync.aligned.m8n8.x4.shared.b16 {%0,%1,%2,%3}, [%4];"
                 : "=r"(r[0]), "=r"(r[1]), "=r"(r[2]), "=r"(r[3]) : "r"(addr));
}
__device__ __forceinline__ void mma16816(float (&d)[4], const uint32_t (&a)[4],
                                         uint32_t b0, uint32_t b1) {
    asm volatile("mma.sync.aligned.m16n8k16.row.col.f32.f16.f16.f32 "
                 "{%0,%1,%2,%3}, {%4,%5,%6,%7}, {%8,%9}, {%0,%1,%2,%3};"
                 : "+f"(d[0]), "+f"(d[1]), "+f"(d[2]), "+f"(d[3])
                 : "r"(a[0]), "r"(a[1]), "r"(a[2]), "r"(a[3]), "r"(b0), "r"(b1));
}
// A fragment (m16k16, row-major src): rows mrow.., cols kc..
__device__ __forceinline__ uint32_t a_addr(uint32_t base, int mrow, int kc, int P, int lane) {
    return base + (uint32_t)((mrow + (lane & 15)) * P + kc + ((lane >> 4) << 3)) * 2;
}
// B fragment pair (two n8 tiles, k16), src rows = n (k-contiguous)
__device__ __forceinline__ uint32_t b_addr(uint32_t base, int nrow, int kc, int P, int lane) {
    return base + (uint32_t)((nrow + (lane & 7) + ((lane >> 4) << 3)) * P + kc +
                             (((lane >> 3) & 1) << 3)) * 2;
}

// stage a fp16 row-major [128r][128c] tile into pitched smem (pitch 136 hw)
#define PP 136
__device__ __forceinline__ void stage128(uint32_t dst, const f16* __restrict__ src, int t) {
    #pragma unroll
    for (int i = 0; i < 8; i++) {
        int idx = t + i * 256;
        int r = idx >> 4, s8 = (idx & 15) << 3;
        cpa16(dst + (uint32_t)(r * PP + s8) * 2, src + (size_t)r * C + s8);
    }
}

// warp GEMM over HALF the N dim: acc[8][4] += A(16x128) * W^T(64x128), cols h*64..
__device__ __forceinline__ void gemm_half(float (*acc)[4], const uint32_t a_all[8][4],
                                          uint32_t wbase, int lane, int h) {
    #pragma unroll
    for (int n2 = 0; n2 < 4; n2++) {
        #pragma unroll
        for (int kk = 0; kk < 8; kk++) {
            uint32_t b[4];
            ldsm4(b, b_addr(wbase, (h * 4 + n2) * 16, kk * 16, PP, lane));
            mma16816(acc[n2 * 2],     a_all[kk], b[0], b[1]);
            mma16816(acc[n2 * 2 + 1], a_all[kk], b[2], b[3]);
        }
    }
}

// gated projection pass: res_pk[h][nt][r] = pack(f16: (P+bp)*sigm(G+bg)*mask)
__device__ __forceinline__ void proj_pass(uint32_t gateW, uint32_t projW,
                                          const float* bP, const float* bG,
                                          const uint32_t a_all[8][4],
                                          float m0, float m1, int lane,
                                          uint32_t res_pk[2][8][2]) {
    #pragma unroll
    for (int h = 0; h < 2; h++) {
        float acc[8][4];
        #pragma unroll
        for (int i = 0; i < 8; i++) {
            acc[i][0] = 0.f; acc[i][1] = 0.f; acc[i][2] = 0.f; acc[i][3] = 0.f;
        }
        gemm_half(acc, a_all, gateW, lane, h);
        uint32_t gate_pk[8][2];
        #pragma unroll
        for (int nt = 0; nt < 8; nt++) {
            int col = (h * 8 + nt) * 8 + (lane & 3) * 2;
            float g0 = bG[col], g1 = bG[col + 1];
            __half2 h0 = __floats2half2_rn(sigm(acc[nt][0] + g0), sigm(acc[nt][1] + g1));
            __half2 h1 = __floats2half2_rn(sigm(acc[nt][2] + g0), sigm(acc[nt][3] + g1));
            gate_pk[nt][0] = *reinterpret_cast<uint32_t*>(&h0);
            gate_pk[nt][1] = *reinterpret_cast<uint32_t*>(&h1);
        }
        #pragma unroll
        for (int i = 0; i < 8; i++) {
            acc[i][0] = 0.f; acc[i][1] = 0.f; acc[i][2] = 0.f; acc[i][3] = 0.f;
        }
        gemm_half(acc, a_all, projW, lane, h);
        #pragma unroll
        for (int nt = 0; nt < 8; nt++) {
            int col = (h * 8 + nt) * 8 + (lane & 3) * 2;
            float p0 = bP[col], p1 = bP[col + 1];
            float2 gf0 = __half22float2(*reinterpret_cast<__half2*>(&gate_pk[nt][0]));
            float2 gf1 = __half22float2(*reinterpret_cast<__half2*>(&gate_pk[nt][1]));
            __half2 r0 = __floats2half2_rn((acc[nt][0] + p0) * gf0.x * m0,
                                           (acc[nt][1] + p1) * gf0.y * m0);
            __half2 r1 = __floats2half2_rn((acc[nt][2] + p0) * gf1.x * m1,
                                           (acc[nt][3] + p1) * gf1.y * m1);
            res_pk[h][nt][0] = *reinterpret_cast<uint32_t*>(&r0);
            res_pk[h][nt][1] = *reinterpret_cast<uint32_t*>(&r1);
        }
    }
}

// epilogue: packed results -> smem transpose stage -> channel-major global
__device__ __forceinline__ void epi_store(f16* __restrict__ outg, f16* stage,
                                          const uint32_t res_pk[2][8][2],
                                          size_t r0, int t, int lane, int w) {
    #pragma unroll
    for (int h = 0; h < 2; h++) {
        #pragma unroll
        for (int nt = 0; nt < 8; nt++) {
            int col = (h * 8 + nt) * 8 + (lane & 3) * 2;
            int row0 = w * 16 + (lane >> 2), row1 = row0 + 8;
            __half2 v0 = *reinterpret_cast<const __half2*>(&res_pk[h][nt][0]);
            __half2 v1 = *reinterpret_cast<const __half2*>(&res_pk[h][nt][1]);
            stage[col * 128 + row0]       = __low2half(v0);
            stage[(col + 1) * 128 + row0] = __high2half(v0);
            stage[col * 128 + row1]       = __low2half(v1);
            stage[(col + 1) * 128 + row1] = __high2half(v1);
        }
    }
    __syncthreads();
    #pragma unroll
    for (int i = 0; i < 8; i++) {
        int idx = t + i * 256, cc = idx >> 4, seg = (idx & 15) << 3;
        *(uint4*)&outg[(size_t)cc * NR + r0 + seg] = *(const uint4*)&stage[cc * 128 + seg];
    }
}

// ---------------- K1: input LayerNorm -> fp16 -------------------------------
__global__ __launch_bounds__(256) void k_ln_in(const float* __restrict__ z,
                                               const float* __restrict__ g,
                                               const float* __restrict__ b) {
    int w = threadIdx.x >> 5, l = threadIdx.x & 31;
    size_t row = (size_t)blockIdx.x * 8 + w;
    float4 v = *(const float4*)&z[row * C + l * 4];
    float s = v.x + v.y + v.z + v.w;
    float s2 = v.x * v.x + v.y * v.y + v.z * v.z + v.w * v.w;
    #pragma unroll
    for (int o = 16; o > 0; o >>= 1) {
        s += __shfl_xor_sync(0xFFFFFFFFu, s, o);
        s2 += __shfl_xor_sync(0xFFFFFFFFu, s2, o);
    }
    float mu = s * (1.f / 128.f);
    float var = s2 * (1.f / 128.f) - mu * mu;
    float rs = rsqrtf(var + 1e-5f);
    float4 gg = *(const float4*)&g[l * 4];
    float4 bb = *(const float4*)&b[l * 4];
    __half2 p0 = __floats2half2_rn((v.x - mu) * rs * gg.x + bb.x,
                                   (v.y - mu) * rs * gg.y + bb.y);
    __half2 p1 = __floats2half2_rn((v.z - mu) * rs * gg.z + bb.z,
                                   (v.w - mu) * rs * gg.w + bb.w);
    uint2 pk = make_uint2(*reinterpret_cast<uint32_t*>(&p0), *reinterpret_cast<uint32_t*>(&p1));
    *reinterpret_cast<uint2*>(&g_zn[row * C + l * 4]) = pk;
}

// ---------------- K2: rsq ----------------------------------------------------
__global__ void k_rsq(const float* __restrict__ mask) {
    __shared__ float mi[8][512];
    int i0 = blockIdx.x * 8;
    int tid = threadIdx.x;
    for (int idx = tid; idx < 8 * 512; idx += 256)
        mi[idx >> 9][idx & 511] = mask[(size_t)(i0 + (idx >> 9)) * L + (idx & 511)];
    __syncthreads();
    for (int j = tid; j < L; j += 256) {
        float s[8];
        #pragma unroll
        for (int ii = 0; ii < 8; ii++) s[ii] = 0.f;
        for (int k = 0; k < L; k += 4) {
            float4 m4 = *(const float4*)&mask[(size_t)j * L + k];
            float mv[4] = {m4.x, m4.y, m4.z, m4.w};
            #pragma unroll
            for (int q = 0; q < 4; q++)
                #pragma unroll
                for (int ii = 0; ii < 8; ii++) s[ii] = fmaf(mi[ii][k + q], mv[q], s[ii]);
        }
        #pragma unroll
        for (int ii = 0; ii < 8; ii++)
            g_rsq[(size_t)(i0 + ii) * L + j] = rsqrtf(fmaxf(s[ii], 1.f));
    }
}

// ---------------- K0: weights fp32 -> fp16 -----------------------------------
__global__ void k_wconv(const float* __restrict__ Wap, const float* __restrict__ Wbp,
                        const float* __restrict__ Wag, const float* __restrict__ Wbg,
                        const float* __restrict__ Wg,  const float* __restrict__ Wo) {
    const float* src[6] = {Wap, Wbp, Wag, Wbg, Wg, Wo};
    int m = blockIdx.y;
    const float* W = src[m];
    int idx = (blockIdx.x * 256 + threadIdx.x) * 4;
    float4 v = *(const float4*)&W[idx];
    __half2 p0 = __floats2half2_rn(v.x, v.y);
    __half2 p1 = __floats2half2_rn(v.z, v.w);
    *(uint2*)&g_wb[m * 16384 + idx] =
        make_uint2(*reinterpret_cast<uint32_t*>(&p0), *reinterpret_cast<uint32_t*>(&p1));
}

// ---------------- K3: fused projections (HMMA, 2 blocks/SM) ------------------
// smem: Xs @0 (34816) | W0 @34816 (34816) | W1 @69632 (34816) | bias @104448
#define PROJ_SMEM (34816 * 3 + 5 * 128 * 4)

__global__ __launch_bounds__(256, 2) void k_proj(
    const float* __restrict__ bap, const float* __restrict__ bag,
    const float* __restrict__ bbp, const float* __restrict__ bbg,
    const float* __restrict__ bgp, const float* __restrict__ mask) {
    extern __shared__ char sm[];
    const uint32_t sb = smem_u32(sm);
    const uint32_t Xs = sb, W0 = sb + 34816, W1 = sb + 69632;
    f16* stage = (f16*)(sm + 34816);    // aliases W0 (dead when epilogues run)
    float* sbias = (float*)(sm + 104448);
    const int t = threadIdx.x, lane = t & 31, w = t >> 5;
    const size_t r0 = (size_t)blockIdx.x * 128;

    stage128(Xs, g_zn + r0 * C, t);
    stage128(W0, g_wb + 2 * 16384, t);   // Wag
    stage128(W1, g_wb + 0 * 16384, t);   // Wap
    cpa_commit();
    if (t < 128) {
        sbias[t] = bap[t]; sbias[128 + t] = bag[t]; sbias[256 + t] = bbp[t];
        sbias[384 + t] = bbg[t]; sbias[512 + t] = bgp[t];
    }
    cpa_wait<0>();
    __syncthreads();

    uint32_t a_all[8][4];
    #pragma unroll
    for (int kk = 0; kk < 8; kk++)
        ldsm4(a_all[kk], a_addr(Xs, w * 16, kk * 16, PP, lane));
    __syncthreads();                     // all warps done reading Xs

    stage128(Xs, g_wb + 3 * 16384, t);   // prefetch Wbg -> Xs
    cpa_commit();

    const float m0 = mask[r0 + w * 16 + (lane >> 2)];
    const float m1 = mask[r0 + w * 16 + 8 + (lane >> 2)];

    uint32_t res_pk[2][8][2];

    // ---- pass a: gate=Wag(W0), proj=Wap(W1) ----
    proj_pass(W0, W1, sbias, sbias + 128, a_all, m0, m1, lane, res_pk);
    __syncthreads();                     // W0/W1 readers done

    stage128(W1, g_wb + 1 * 16384, t);   // prefetch Wbp -> W1
    cpa_commit();

    epi_store(g_at, stage, res_pk, r0, t, lane, w);

    cpa_wait<0>();                       // Wbg (Xs) and Wbp (W1) landed
    __syncthreads();

    // ---- pass b: gate=Wbg(Xs), proj=Wbp(W1) ----
    proj_pass(Xs, W1, sbias + 256, sbias + 384, a_all, m0, m1, lane, res_pk);
    __syncthreads();                     // Xs/W1 readers done

    stage128(Xs, g_wb + 4 * 16384, t);   // prefetch Wg -> Xs
    cpa_commit();

    epi_store(g_bt, stage, res_pk, r0, t, lane, w);

    cpa_wait<0>();                       // Wg landed
    __syncthreads();

    // ---- gate pass: sigm(zn Wg + bg), row-major ----
    #pragma unroll
    for (int h = 0; h < 2; h++) {
        float acc[8][4];
        #pragma unroll
        for (int i = 0; i < 8; i++) {
            acc[i][0] = 0.f; acc[i][1] = 0.f; acc[i][2] = 0.f; acc[i][3] = 0.f;
        }
        gemm_half(acc, a_all, Xs, lane, h);
        #pragma unroll
        for (int nt = 0; nt < 8; nt++) {
            int col = (h * 8 + nt) * 8 + (lane & 3) * 2;
            int row0 = w * 16 + (lane >> 2), row1 = row0 + 8;
            float b0 = sbias[512 + col], b1 = sbias[512 + col + 1];
            __half2 h0 = __floats2half2_rn(sigm(acc[nt][0] + b0), sigm(acc[nt][1] + b1));
            __half2 h1 = __floats2half2_rn(sigm(acc[nt][2] + b0), sigm(acc[nt][3] + b1));
            *(uint32_t*)&g_gate[(r0 + row0) * C + col] = *reinterpret_cast<uint32_t*>(&h0);
            *(uint32_t*)&g_gate[(r0 + row1) * C + col] = *reinterpret_cast<uint32_t*>(&h1);
        }
    }
}

// ---------------- K4: triangle contraction (HMMA, per channel) ---------------
#define PT 72
#define TRI_SMEM (4 * 128 * PT * 2)   // 73728

__global__ __launch_bounds__(256, 2) void k_tri() {
    extern __shared__ char sm[];
    const uint32_t sb = smem_u32(sm);
    const int t = threadIdx.x, lane = t & 31, w = t >> 5;
    const int c = blockIdx.z, i0 = blockIdx.y * 128, j0 = blockIdx.x * 128;
    const f16* A = g_at + (size_t)c * NR + (size_t)i0 * L;
    const f16* Bg = g_bt + (size_t)c * NR + (size_t)j0 * L;
    const uint32_t Ab[2] = {sb, sb + 18432};
    const uint32_t Bb[2] = {sb + 36864, sb + 55296};

    // preload chunk 0
    {
        #pragma unroll
        for (int i = 0; i < 4; i++) {
            int idx = t + i * 256, r = idx >> 3, s = (idx & 7) << 3;
            cpa16(Ab[0] + (uint32_t)(r * PT + s) * 2, A + (size_t)r * L + s);
        }
        #pragma unroll
        for (int i = 0; i < 4; i++) {
            int idx = t + i * 256, r = idx >> 3, s = (idx & 7) << 3;
            cpa16(Bb[0] + (uint32_t)(r * PT + s) * 2, Bg + (size_t)r * L + s);
        }
        cpa_commit();
    }

    float acc[16][4];
    #pragma unroll
    for (int i = 0; i < 16; i++)
        #pragma unroll
        for (int q = 0; q < 4; q++) acc[i][q] = 0.f;
    const int wi = (w & 3) * 32, wj = (w >> 2) * 64;

    for (int kb = 0; kb < 8; kb++) {
        int b = kb & 1;
        if (kb < 7) {
            int nb = b ^ 1;
            #pragma unroll
            for (int i = 0; i < 4; i++) {
                int idx = t + i * 256, r = idx >> 3, s = (idx & 7) << 3;
                cpa16(Ab[nb] + (uint32_t)(r * PT + s) * 2, A + (size_t)r * L + (kb + 1) * 64 + s);
            }
            #pragma unroll
            for (int i = 0; i < 4; i++) {
                int idx = t + i * 256, r = idx >> 3, s = (idx & 7) << 3;
                cpa16(Bb[nb] + (uint32_t)(r * PT + s) * 2, Bg + (size_t)r * L + (kb + 1) * 64 + s);
            }
            cpa_commit();
            cpa_wait<1>();
        } else {
            cpa_wait<0>();
        }
        __syncthreads();
        #pragma unroll
        for (int kk = 0; kk < 4; kk++) {
            uint32_t a0[4], a1[4];
            ldsm4(a0, a_addr(Ab[b], wi, kk * 16, PT, lane));
            ldsm4(a1, a_addr(Ab[b], wi + 16, kk * 16, PT, lane));
            #pragma unroll
            for (int nt2 = 0; nt2 < 4; nt2++) {
                uint32_t bb[4];
                ldsm4(bb, b_addr(Bb[b], wj + nt2 * 16, kk * 16, PT, lane));
                mma16816(acc[nt2 * 2],         a0, bb[0], bb[1]);
                mma16816(acc[nt2 * 2 + 1],     a0, bb[2], bb[3]);
                mma16816(acc[8 + nt2 * 2],     a1, bb[0], bb[1]);
                mma16816(acc[8 + nt2 * 2 + 1], a1, bb[2], bb[3]);
            }
        }
        __syncthreads();
    }

    float* xp = g_xt + (size_t)c * NR;
    #pragma unroll
    for (int mt = 0; mt < 2; mt++) {
        int row0 = i0 + wi + mt * 16 + (lane >> 2);
        #pragma unroll
        for (int nt = 0; nt < 8; nt++) {
            int col = j0 + wj + nt * 8 + (lane & 3) * 2;
            float* d = acc[mt * 8 + nt];
            size_t o0 = (size_t)row0 * L + col;
            size_t o1 = (size_t)(row0 + 8) * L + col;
            float2 rv0 = *(const float2*)&g_rsq[o0];
            float2 rv1 = *(const float2*)&g_rsq[o1];
            *(float2*)&xp[o0] = make_float2(d[0] * rv0.x, d[1] * rv0.y);
            *(float2*)&xp[o1] = make_float2(d[2] * rv1.x, d[3] * rv1.y);
        }
    }
}

// ---------------- K5: LN-out stats + normalize + transpose -> fp16 [r][c] ----
__global__ __launch_bounds__(128) void k_lnT(const float* __restrict__ lng,
                                             const float* __restrict__ lnb) {
    extern __shared__ float raw[];  // [128][132]
    const int t = threadIdx.x, w = t >> 5, l = t & 31;
    const size_t r0 = (size_t)blockIdx.x * 128;
    #pragma unroll 4
    for (int cc = 0; cc < 32; cc++) {
        int c = w * 32 + cc;
        float4 v = *(const float4*)&g_xt[(size_t)c * NR + r0 + l * 4];
        *(float4*)&raw[c * 132 + l * 4] = v;
    }
    __syncthreads();
    float s = 0.f, s2 = 0.f;
    #pragma unroll 8
    for (int c = 0; c < C; c++) {
        float v = raw[c * 132 + t];
        s += v; s2 += v * v;
    }
    float mu = s * (1.f / 128.f);
    float var = s2 * (1.f / 128.f) - mu * mu;
    float rs = rsqrtf(var + 1e-5f);
    f16* xr = g_xn + (r0 + t) * C;
    #pragma unroll
    for (int seg = 0; seg < 16; seg++) {
        uint32_t u[4];
        #pragma unroll
        for (int q = 0; q < 4; q++) {
            int c = seg * 8 + q * 2;
            float v0 = (raw[c * 132 + t] - mu) * rs * lng[c] + lnb[c];
            float v1 = (raw[(c + 1) * 132 + t] - mu) * rs * lng[c + 1] + lnb[c + 1];
            __half2 p = __floats2half2_rn(v0, v1);
            u[q] = *reinterpret_cast<uint32_t*>(&p);
        }
        *reinterpret_cast<uint4*>(xr + seg * 8) = make_uint4(u[0], u[1], u[2], u[3]);
    }
}

// ---------------- K6: output GEMM + gate epilogue (HMMA, 2 blocks/SM) --------
#define OUT_SMEM (34816 * 2 + 512)

__global__ __launch_bounds__(256, 2) void k_out(const float* __restrict__ bo,
                                                const float* __restrict__ mask,
                                                float* __restrict__ OUT) {
    extern __shared__ char sm[];
    const uint32_t sb = smem_u32(sm);
    const uint32_t Xs = sb, Ws = sb + 34816;
    float* sbo = (float*)(sm + 69632);
    const int t = threadIdx.x, lane = t & 31, w = t >> 5;
    const size_t r0 = (size_t)blockIdx.x * 128;

    stage128(Xs, g_xn + r0 * C, t);
    stage128(Ws, g_wb + 5 * 16384, t);
    cpa_commit();
    if (t < 128) sbo[t] = bo[t];
    cpa_wait<0>();
    __syncthreads();

    uint32_t a_all[8][4];
    #pragma unroll
    for (int kk = 0; kk < 8; kk++)
        ldsm4(a_all[kk], a_addr(Xs, w * 16, kk * 16, PP, lane));

    const float m0 = mask[r0 + w * 16 + (lane >> 2)];
    const float m1 = mask[r0 + w * 16 + 8 + (lane >> 2)];

    #pragma unroll
    for (int h = 0; h < 2; h++) {
        float acc[8][4];
        #pragma unroll
        for (int i = 0; i < 8; i++) {
            acc[i][0] = 0.f; acc[i][1] = 0.f; acc[i][2] = 0.f; acc[i][3] = 0.f;
        }
        gemm_half(acc, a_all, Ws, lane, h);
        #pragma unroll
        for (int nt = 0; nt < 8; nt++) {
            int col = (h * 8 + nt) * 8 + (lane & 3) * 2;
            int row0 = w * 16 + (lane >> 2), row1 = row0 + 8;
            float b0 = sbo[col], b1 = sbo[col + 1];
            __half2 gg0 = *(const __half2*)&g_gate[(r0 + row0) * C + col];
            __half2 gg1 = *(const __half2*)&g_gate[(r0 + row1) * C + col];
            float2 o0 = make_float2((acc[nt][0] + b0) * __low2float(gg0) * m0,
                                    (acc[nt][1] + b1) * __high2float(gg0) * m0);
            float2 o1 = make_float2((acc[nt][2] + b0) * __low2float(gg1) * m1,
                                    (acc[nt][3] + b1) * __high2float(gg1) * m1);
            *(float2*)&OUT[(r0 + row0) * C + col] = o0;
            *(float2*)&OUT[(r0 + row1) * C + col] = o1;
        }
    }
}

// ---------------- launch -----------------------------------------------------
extern "C" void kernel_launch(void* const* d_in, const int* in_sizes, int n_in,
                              void* d_out, int out_size) {
    const float* z       = (const float*)d_in[0];
    const float* mask    = (const float*)d_in[1];
    const float* ln_in_g = (const float*)d_in[2];
    const float* ln_in_b = (const float*)d_in[3];
    const float* Wap = (const float*)d_in[4],  *bap = (const float*)d_in[5];
    const float* Wbp = (const float*)d_in[6],  *bbp = (const float*)d_in[7];
    const float* Wag = (const float*)d_in[8],  *bag = (const float*)d_in[9];
    const float* Wbg = (const float*)d_in[10], *bbg = (const float*)d_in[11];
    const float* lng = (const float*)d_in[12], *lnb = (const float*)d_in[13];
    const float* Wo  = (const float*)d_in[14], *bo  = (const float*)d_in[15];
    const float* Wg  = (const float*)d_in[16], *bg  = (const float*)d_in[17];
    float* out = (float*)d_out;

    cudaFuncSetAttribute(k_proj, cudaFuncAttributeMaxDynamicSharedMemorySize, PROJ_SMEM);
    cudaFuncSetAttribute(k_tri,  cudaFuncAttributeMaxDynamicSharedMemorySize, TRI_SMEM);
    cudaFuncSetAttribute(k_lnT,  cudaFuncAttributeMaxDynamicSharedMemorySize, 128 * 132 * 4);
    cudaFuncSetAttribute(k_out,  cudaFuncAttributeMaxDynamicSharedMemorySize, OUT_SMEM);

    k_ln_in<<<NR / 8, 256>>>(z, ln_in_g, ln_in_b);
    k_rsq<<<64, 256>>>(mask);
    k_wconv<<<dim3(16, 6), 256>>>(Wap, Wbp, Wag, Wbg, Wg, Wo);
    k_proj<<<NR / 128, 256, PROJ_SMEM>>>(bap, bag, bbp, bbg, bg, mask);
    k_tri<<<dim3(4, 4, 128), 256, TRI_SMEM>>>();
    k_lnT<<<NR / 128, 128, 128 * 132 * 4>>>(lng, lnb);
    k_out<<<NR / 128, 256, OUT_SMEM>>>(bo, mask, out);
}